// round 2
// baseline (speedup 1.0000x reference)
#include <cuda_runtime.h>

// ---------------------------------------------------------------------------
// BodyTransformer fused kernel (fp32, f32x2-packed FMA), sm_103a
// B=4096, N=32, D=128, E=256, H=8, DH=32, F=1024, L=6 (shared layer weights)
// ---------------------------------------------------------------------------

#define XS_STRIDE 257   // xs[32][257]  (token-major residual state)
#define AT_STRIDE 36    // aT[k][36]    (k-major GEMM input; 16B-aligned rows, 4-way max conflict)
#define KT_STRIDE 33    // kT[d][33]    (conflict-free scalar access)
#define QS_STRIDE 264   // qs/vs[32][264] (16B-aligned rows)

// Pre-transposed weights (written each launch by transpose kernels)
__device__ float g_WqkvT[256 * 768];   // [k][c] ; c in [0,768)
__device__ float g_WoT[256 * 256];     // [k][c]

static __device__ __forceinline__ void ffma2(unsigned long long& d,
                                             unsigned long long a,
                                             unsigned long long b) {
    asm("fma.rn.f32x2 %0, %1, %2, %0;" : "+l"(d) : "l"(a), "l"(b));
}
static __device__ __forceinline__ unsigned long long pack2(float x) {
    union { unsigned long long u; float2 f; } cv;
    cv.f = make_float2(x, x);
    return cv.u;
}
static __device__ __forceinline__ float2 unpack2(unsigned long long v) {
    union { unsigned long long u; float2 f; } cv;
    cv.u = v;
    return cv.f;
}

// out[t][c] = sum_k aT[k][t] * W[k*ldw + c], tokens packed in pairs.
// aT rows are broadcast LDS.128; weight loads are lane-coalesced LDG.32,
// double-buffered one 8-k block ahead to hide L2 latency.
static __device__ __forceinline__ void gemm_colW(const float* __restrict__ aT,
                                                 const float* __restrict__ Wc,
                                                 int ldw, int K,
                                                 unsigned long long* acc) {
#pragma unroll
    for (int p = 0; p < 16; ++p) acc[p] = 0ULL;
    const int nblk = K >> 3;
    float cur[8], nxt[8];
#pragma unroll
    for (int kk = 0; kk < 8; ++kk) cur[kk] = Wc[kk * ldw];
    for (int blk = 0; blk < nblk; ++blk) {
        const int nb = (blk + 1 < nblk) ? blk + 1 : blk;
        const float* wn = Wc + (nb << 3) * ldw;
#pragma unroll
        for (int kk = 0; kk < 8; ++kk) nxt[kk] = wn[kk * ldw];
        const float* arow0 = aT + (blk << 3) * AT_STRIDE;
#pragma unroll
        for (int kk = 0; kk < 8; ++kk) {
            const unsigned long long wpk = pack2(cur[kk]);
            const double2* row = (const double2*)(arow0 + kk * AT_STRIDE);
#pragma unroll
            for (int i = 0; i < 8; ++i) {
                double2 a = row[i];
                ffma2(acc[2 * i],     __double_as_longlong(a.x), wpk);
                ffma2(acc[2 * i + 1], __double_as_longlong(a.y), wpk);
            }
        }
#pragma unroll
        for (int kk = 0; kk < 8; ++kk) cur[kk] = nxt[kk];
    }
}

// LayerNorm xs -> outT (k-major). lane = token, wid = column-block of 32.
static __device__ __forceinline__ void layer_norm_block(
    const float* __restrict__ xs, const float* __restrict__ g,
    const float* __restrict__ bb, float* __restrict__ outT,
    float* __restrict__ red, float* __restrict__ red2, int lane, int wid) {
    const float* row = xs + lane * XS_STRIDE + wid * 32;
    float s = 0.f, s2 = 0.f;
#pragma unroll
    for (int i = 0; i < 32; ++i) {
        float v = row[i];
        s += v;
        s2 = fmaf(v, v, s2);
    }
    red[wid * 32 + lane] = s;
    red2[wid * 32 + lane] = s2;
    __syncthreads();
    float t = 0.f, t2 = 0.f;
#pragma unroll
    for (int w = 0; w < 8; ++w) {
        t += red[w * 32 + lane];
        t2 += red2[w * 32 + lane];
    }
    const float mean = t * 0.00390625f;
    const float var = t2 * 0.00390625f - mean * mean;
    const float rstd = rsqrtf(var + 1e-5f);
#pragma unroll
    for (int i = 0; i < 32; ++i) {
        const int c = wid * 32 + i;
        outT[c * AT_STRIDE + lane] = (row[i] - mean) * rstd * g[c] + bb[c];
    }
    __syncthreads();
}

// ---------------------------------------------------------------------------
// Main fused kernel: one CTA per batch item, 6 layers in shared memory.
// smem: xs(8224) | red(256) | red2(256) | S(46080)  = 54816 floats = 219264 B
// S: hT[256][36] @0 ; qs[32][264] @9216 ; kT[256][33] @17664 ; vs[32][264] @26112
//    uT[1024][36] @9216 (FFN phase, overlaps qs/kT/vs)
// ---------------------------------------------------------------------------
__global__ void __launch_bounds__(256, 1)
bt_main(float* __restrict__ x,  // [4096][32][256] in/out (d_out)
        const float* __restrict__ bqkv, const float* __restrict__ bo,
        const float* __restrict__ ln1g, const float* __restrict__ ln1b,
        const float* __restrict__ ln2g, const float* __restrict__ ln2b,
        const float* __restrict__ W1, const float* __restrict__ b1,
        const float* __restrict__ W2, const float* __restrict__ b2) {
    extern __shared__ float sm[];
    float* xs = sm;                 // 32*257
    float* red = sm + 8224;         // 256
    float* red2 = sm + 8480;        // 256
    float* S = sm + 8736;
    float* hT = S;                  // 256*36 (also oT / h2T)
    float* qs = S + 9216;           // 32*264
    float* kT = S + 17664;          // 256*33
    float* vs = S + 26112;          // 32*264
    float* uT = S + 9216;           // 1024*36 (FFN phase)

    const int tid = threadIdx.x;
    const int lane = tid & 31;
    const int wid = tid >> 5;
    const int b = blockIdx.x;
    float* gx = x + b * 8192;

    for (int i = tid; i < 8192; i += 256)
        xs[(i >> 8) * XS_STRIDE + (i & 255)] = gx[i];
    __syncthreads();

    unsigned long long acc[16];

    for (int layer = 0; layer < 6; ++layer) {
        // ---- LN1 -> hT
        layer_norm_block(xs, ln1g, ln1b, hT, red, red2, lane, wid);

        // ---- QKV: qkv[t][c] = sum_k hT[k][t] * WqkvT[k][c] + bqkv[c]
        for (int pass = 0; pass < 3; ++pass) {
            const int c = tid + (pass << 8);
            gemm_colW(hT, g_WqkvT + c, 768, 256, acc);
            const float bias = bqkv[c];
            if (pass == 0) {
#pragma unroll
                for (int p = 0; p < 16; ++p) {
                    float2 f = unpack2(acc[p]);
                    qs[(2 * p) * QS_STRIDE + c] = f.x + bias;
                    qs[(2 * p + 1) * QS_STRIDE + c] = f.y + bias;
                }
            } else if (pass == 1) {
                const int d = tid;  // c - 256
#pragma unroll
                for (int p = 0; p < 16; ++p) {
                    float2 f = unpack2(acc[p]);
                    kT[d * KT_STRIDE + 2 * p] = f.x + bias;
                    kT[d * KT_STRIDE + 2 * p + 1] = f.y + bias;
                }
            } else {
                const int cc = tid;  // c - 512
#pragma unroll
                for (int p = 0; p < 16; ++p) {
                    float2 f = unpack2(acc[p]);
                    vs[(2 * p) * QS_STRIDE + cc] = f.x + bias;
                    vs[(2 * p + 1) * QS_STRIDE + cc] = f.y + bias;
                }
            }
        }
        __syncthreads();

        // ---- Attention: warp = head. Banded mask |i-j|<=1.
        {
            const int h = wid;
            float kreg[32];
#pragma unroll
            for (int d = 0; d < 32; ++d)
                kreg[d] = kT[(h * 32 + d) * KT_STRIDE + lane];
            const float SC = 0.17677669529663689f;  // 1/sqrt(32)
            for (int i = 0; i < 32; ++i) {
                const float4* qrow = (const float4*)(qs + i * QS_STRIDE + h * 32);
                float s = 0.f;
#pragma unroll
                for (int d4 = 0; d4 < 8; ++d4) {
                    float4 q = qrow[d4];
                    s = fmaf(q.x, kreg[4 * d4 + 0], s);
                    s = fmaf(q.y, kreg[4 * d4 + 1], s);
                    s = fmaf(q.z, kreg[4 * d4 + 2], s);
                    s = fmaf(q.w, kreg[4 * d4 + 3], s);
                }
                s *= SC;
                int dj = lane - i;
                if (dj < 0) dj = -dj;
                if (dj > 1) s -= 1e9f;  // additive mask, matches reference
                float m = s;
#pragma unroll
                for (int off = 16; off; off >>= 1)
                    m = fmaxf(m, __shfl_xor_sync(0xffffffffu, m, off));
                const float e = expf(s - m);  // masked entries underflow to 0 exactly
                float sum = e;
#pragma unroll
                for (int off = 16; off; off >>= 1)
                    sum += __shfl_xor_sync(0xffffffffu, sum, off);
                const float w = e / sum;
                // o[i][d=lane] = sum over the <=3 unmasked neighbors
                float o = 0.f;
                const int j0 = (i > 0) ? i - 1 : 0;
                const int j1 = (i < 31) ? i + 1 : 31;
                for (int j = j0; j <= j1; ++j) {
                    const float wj = __shfl_sync(0xffffffffu, w, j);
                    o = fmaf(wj, vs[j * QS_STRIDE + h * 32 + lane], o);
                }
                hT[(h * 32 + lane) * AT_STRIDE + i] = o;  // oT, k-major
            }
        }
        __syncthreads();

        // ---- x += o @ Wo^T + bo
        {
            const int c = tid;
            gemm_colW(hT, g_WoT + c, 256, 256, acc);
            const float bias = bo[c];
#pragma unroll
            for (int p = 0; p < 16; ++p) {
                float2 f = unpack2(acc[p]);
                xs[(2 * p) * XS_STRIDE + c] += f.x + bias;
                xs[(2 * p + 1) * XS_STRIDE + c] += f.y + bias;
            }
        }
        __syncthreads();

        // ---- LN2 -> hT
        layer_norm_block(xs, ln2g, ln2b, hT, red, red2, lane, wid);

        // ---- FFN1: u[t][f] = relu(sum_k hT[k][t] * W1[k][f] + b1[f])
        for (int pass = 0; pass < 4; ++pass) {
            const int f = tid + (pass << 8);
            gemm_colW(hT, W1 + f, 1024, 256, acc);
            const float bias = b1[f];
#pragma unroll
            for (int p = 0; p < 16; ++p) {
                float2 v = unpack2(acc[p]);
                uT[f * AT_STRIDE + 2 * p] = fmaxf(v.x + bias, 0.f);
                uT[f * AT_STRIDE + 2 * p + 1] = fmaxf(v.y + bias, 0.f);
            }
        }
        __syncthreads();

        // ---- FFN2: x += u @ W2 + b2
        {
            const int c = tid;
            gemm_colW(uT, W2 + c, 256, 1024, acc);
            const float bias = b2[c];
#pragma unroll
            for (int p = 0; p < 16; ++p) {
                float2 f = unpack2(acc[p]);
                xs[(2 * p) * XS_STRIDE + c] += f.x + bias;
                xs[(2 * p + 1) * XS_STRIDE + c] += f.y + bias;
            }
        }
        __syncthreads();
    }

    for (int i = tid; i < 8192; i += 256)
        gx[i] = xs[(i >> 8) * XS_STRIDE + (i & 255)];
}

// ---------------------------------------------------------------------------
// Tokenizer: x[b][n][e] = obs[b,:] @ emb_W[n] + emb_b[n] + pos[n]
// grid (n=32, b-tiles of 32). Thread = output column e, 32 batch rows.
// ---------------------------------------------------------------------------
__global__ void __launch_bounds__(256)
bt_tokenize(const float* __restrict__ obs, const float* __restrict__ embW,
            const float* __restrict__ embB, const float* __restrict__ pos,
            float* __restrict__ out) {
    __shared__ float obs_s[32 * 128];
    const int n = blockIdx.x;
    const int b0 = blockIdx.y * 32;
    const int tid = threadIdx.x;

    const float* src = obs + b0 * 128;
    for (int i = tid; i < 4096; i += 256) obs_s[i] = src[i];
    __syncthreads();

    const int e = tid;
    float acc[32];
#pragma unroll
    for (int bb = 0; bb < 32; ++bb) acc[bb] = 0.f;
    const float* wb = embW + n * 32768 + e;  // emb_W[n][d][e], lanes coalesced
    for (int d0 = 0; d0 < 128; d0 += 16) {
        float w[16];
#pragma unroll
        for (int dd = 0; dd < 16; ++dd) w[dd] = wb[(d0 + dd) * 256];
#pragma unroll
        for (int bb = 0; bb < 32; ++bb) {
            const float4* orow = (const float4*)(obs_s + bb * 128 + d0);
            float4 o0 = orow[0], o1 = orow[1], o2 = orow[2], o3 = orow[3];
            float a = acc[bb];
            a = fmaf(o0.x, w[0], a);  a = fmaf(o0.y, w[1], a);
            a = fmaf(o0.z, w[2], a);  a = fmaf(o0.w, w[3], a);
            a = fmaf(o1.x, w[4], a);  a = fmaf(o1.y, w[5], a);
            a = fmaf(o1.z, w[6], a);  a = fmaf(o1.w, w[7], a);
            a = fmaf(o2.x, w[8], a);  a = fmaf(o2.y, w[9], a);
            a = fmaf(o2.z, w[10], a); a = fmaf(o2.w, w[11], a);
            a = fmaf(o3.x, w[12], a); a = fmaf(o3.y, w[13], a);
            a = fmaf(o3.z, w[14], a); a = fmaf(o3.w, w[15], a);
            acc[bb] = a;
        }
    }
    const float add = embB[n * 256 + e] + pos[n * 256 + e];
#pragma unroll
    for (int bb = 0; bb < 32; ++bb)
        out[(b0 + bb) * 8192 + n * 256 + e] = acc[bb] + add;
}

// Transpose Wqkv[768][256] -> g_WqkvT[256][768]
__global__ void bt_transpose_wqkv(const float* __restrict__ src) {
    int idx = blockIdx.x * 256 + threadIdx.x;
    if (idx < 768 * 256) {
        int r = idx >> 8, c = idx & 255;         // src[r][c]
        g_WqkvT[c * 768 + r] = src[idx];
    }
}
// Transpose Wo[256][256] -> g_WoT[256][256]
__global__ void bt_transpose_wo(const float* __restrict__ src) {
    int idx = blockIdx.x * 256 + threadIdx.x;
    if (idx < 256 * 256) {
        int r = idx >> 8, c = idx & 255;
        g_WoT[c * 256 + r] = src[idx];
    }
}

extern "C" void kernel_launch(void* const* d_in, const int* in_sizes, int n_in,
                              void* d_out, int out_size) {
    (void)in_sizes; (void)n_in; (void)out_size;
    const float* obs  = (const float*)d_in[0];
    const float* embW = (const float*)d_in[1];
    const float* embB = (const float*)d_in[2];
    const float* pos  = (const float*)d_in[3];
    const float* Wqkv = (const float*)d_in[4];
    const float* bqkv = (const float*)d_in[5];
    const float* Wo   = (const float*)d_in[6];
    const float* bo   = (const float*)d_in[7];
    const float* ln1g = (const float*)d_in[8];
    const float* ln1b = (const float*)d_in[9];
    const float* ln2g = (const float*)d_in[10];
    const float* ln2b = (const float*)d_in[11];
    const float* W1   = (const float*)d_in[12];
    const float* b1   = (const float*)d_in[13];
    const float* W2   = (const float*)d_in[14];
    const float* b2   = (const float*)d_in[15];
    float* x = (float*)d_out;

    const int SMEM_BYTES = 54816 * 4;  // 219264
    cudaFuncSetAttribute(bt_main, cudaFuncAttributeMaxDynamicSharedMemorySize,
                         SMEM_BYTES);

    bt_transpose_wqkv<<<768, 256>>>(Wqkv);
    bt_transpose_wo<<<256, 256>>>(Wo);
    bt_tokenize<<<dim3(32, 128), 256>>>(obs, embW, embB, pos, x);
    bt_main<<<4096, 256, SMEM_BYTES>>>(x, bqkv, bo, ln1g, ln1b, ln2g, ln2b,
                                       W1, b1, W2, b2);
}

// round 4
// speedup vs baseline: 1.3107x; 1.3107x over previous
#include <cuda_runtime.h>

// ---------------------------------------------------------------------------
// BodyTransformer fused kernel (fp32, f32x2-packed FMA), sm_103a — round 3
// B=4096, N=32, D=128, E=256, H=8, DH=32, F=1024, L=6 (shared layer weights)
// GEMM tiles: 16 tokens x Ct columns per thread (token halves across warps).
// ---------------------------------------------------------------------------

#define XS_STRIDE 257   // xs[32][257]
#define AT_STRIDE 36    // aT[k][36] (k-major GEMM input, 16B-aligned rows)
#define KT_STRIDE 33    // kT[d][33]
#define QS_STRIDE 264   // qs/vs[32][264]

__device__ float g_WqkvT[256 * 768];   // [k][c]
__device__ float g_WoT[256 * 256];     // [k][c]

static __device__ __forceinline__ void ffma2(unsigned long long& d,
                                             unsigned long long a,
                                             unsigned long long b) {
    asm("fma.rn.f32x2 %0, %1, %2, %0;" : "+l"(d) : "l"(a), "l"(b));
}
static __device__ __forceinline__ unsigned long long pack2(float x) {
    union { unsigned long long u; float2 f; } cv;
    cv.f = make_float2(x, x);
    return cv.u;
}
static __device__ __forceinline__ float2 unpack2(unsigned long long v) {
    union { unsigned long long u; float2 f; } cv;
    cv.u = v;
    return cv.f;
}

// out[t][c_j] = sum_k aT[k][t] * W[k*ldw + j*128], 16 tokens (8 f32x2) x CT cols.
// aT: broadcast LDS.128; weights: lane-coalesced LDG.32, NB-deep k prefetch.
template <int CT, int NB>
static __device__ __forceinline__ void gemm16(const float* __restrict__ aT,
                                              const float* __restrict__ Wc,
                                              int ldw, int K,
                                              unsigned long long* acc) {
#pragma unroll
    for (int p = 0; p < 8 * CT; ++p) acc[p] = 0ULL;
    float cur[NB][CT], nxt[NB][CT];
#pragma unroll
    for (int kk = 0; kk < NB; ++kk)
#pragma unroll
        for (int j = 0; j < CT; ++j) cur[kk][j] = Wc[kk * ldw + j * 128];
    const int nblk = K / NB;
    for (int blk = 0; blk < nblk; ++blk) {
        const int nb = (blk + 1 < nblk) ? blk + 1 : blk;
        const float* wn = Wc + nb * NB * ldw;
#pragma unroll
        for (int kk = 0; kk < NB; ++kk)
#pragma unroll
            for (int j = 0; j < CT; ++j) nxt[kk][j] = wn[kk * ldw + j * 128];
        const float* arow0 = aT + blk * NB * AT_STRIDE;
#pragma unroll
        for (int kk = 0; kk < NB; ++kk) {
            const double2* row = (const double2*)(arow0 + kk * AT_STRIDE);
            double2 a0 = row[0], a1 = row[1], a2 = row[2], a3 = row[3];
            unsigned long long av[8];
            av[0] = __double_as_longlong(a0.x); av[1] = __double_as_longlong(a0.y);
            av[2] = __double_as_longlong(a1.x); av[3] = __double_as_longlong(a1.y);
            av[4] = __double_as_longlong(a2.x); av[5] = __double_as_longlong(a2.y);
            av[6] = __double_as_longlong(a3.x); av[7] = __double_as_longlong(a3.y);
#pragma unroll
            for (int j = 0; j < CT; ++j) {
                const unsigned long long wpk = pack2(cur[kk][j]);
#pragma unroll
                for (int t = 0; t < 8; ++t) ffma2(acc[t * CT + j], av[t], wpk);
            }
        }
#pragma unroll
        for (int kk = 0; kk < NB; ++kk)
#pragma unroll
            for (int j = 0; j < CT; ++j) cur[kk][j] = nxt[kk][j];
    }
}

// LayerNorm xs -> outT (k-major). lane = token, wid = column-block of 32.
static __device__ __forceinline__ void layer_norm_block(
    const float* __restrict__ xs, const float* __restrict__ g,
    const float* __restrict__ bb, float* __restrict__ outT,
    float* __restrict__ red, float* __restrict__ red2, int lane, int wid) {
    const float* row = xs + lane * XS_STRIDE + wid * 32;
    float s = 0.f, s2 = 0.f;
#pragma unroll
    for (int i = 0; i < 32; ++i) {
        float v = row[i];
        s += v;
        s2 = fmaf(v, v, s2);
    }
    red[wid * 32 + lane] = s;
    red2[wid * 32 + lane] = s2;
    __syncthreads();
    float t = 0.f, t2 = 0.f;
#pragma unroll
    for (int w = 0; w < 8; ++w) {
        t += red[w * 32 + lane];
        t2 += red2[w * 32 + lane];
    }
    const float mean = t * 0.00390625f;
    const float var = t2 * 0.00390625f - mean * mean;
    const float rstd = rsqrtf(var + 1e-5f);
#pragma unroll
    for (int i = 0; i < 32; ++i) {
        const int c = wid * 32 + i;
        outT[c * AT_STRIDE + lane] = (row[i] - mean) * rstd * g[c] + bb[c];
    }
    __syncthreads();
}

// ---------------------------------------------------------------------------
// Main fused kernel: one CTA per batch item, 6 layers in shared memory.
// smem: xs(8224) | red(256) | red2(256) | S(46080) = 54816 floats = 219264 B
// S: hT[256][36] @0 ; qs[32][264] @9216 ; kT[256][33] @17664 ; vs[32][264] @26112
//    uT[1024][36] @9216 (FFN phase, overlaps qs/kT/vs)
// ---------------------------------------------------------------------------
__global__ void __launch_bounds__(256, 1)
bt_main(float* __restrict__ x,
        const float* __restrict__ bqkv, const float* __restrict__ bo,
        const float* __restrict__ ln1g, const float* __restrict__ ln1b,
        const float* __restrict__ ln2g, const float* __restrict__ ln2b,
        const float* __restrict__ W1, const float* __restrict__ b1,
        const float* __restrict__ W2, const float* __restrict__ b2) {
    extern __shared__ float sm[];
    float* xs = sm;                 // 32*257
    float* red = sm + 8224;
    float* red2 = sm + 8480;
    float* S = sm + 8736;
    float* hT = S;                  // 256*36 (also oT / h2T)
    float* qs = S + 9216;           // 32*264
    float* kT = S + 17664;          // 256*33
    float* vs = S + 26112;          // 32*264
    float* uT = S + 9216;           // 1024*36 (FFN phase)

    const int tid = threadIdx.x;
    const int lane = tid & 31;
    const int wid = tid >> 5;
    const int ct = tid & 127;       // column-thread within half
    const int half16 = (tid >> 7) << 4;  // 0 or 16: token-half base
    const int b = blockIdx.x;
    float* gx = x + b * 8192;

    for (int i = tid; i < 8192; i += 256)
        xs[(i >> 8) * XS_STRIDE + (i & 255)] = gx[i];
    __syncthreads();

    unsigned long long acc[32];

    for (int layer = 0; layer < 6; ++layer) {
        // ---- LN1 -> hT
        layer_norm_block(xs, ln1g, ln1b, hT, red, red2, lane, wid);

        // ---- QKV pass 0: cols [0,384) = q[0..255], k[0..127]
        {
            gemm16<3, 8>(hT + half16, g_WqkvT + ct, 768, 256, acc);
#pragma unroll
            for (int j = 0; j < 3; ++j) {
                const int c = ct + j * 128;
                const float bias = bqkv[c];
#pragma unroll
                for (int t2 = 0; t2 < 8; ++t2) {
                    float2 f = unpack2(acc[t2 * 3 + j]);
                    const int t0 = half16 + 2 * t2;
                    if (j < 2) {
                        qs[t0 * QS_STRIDE + c] = f.x + bias;
                        qs[(t0 + 1) * QS_STRIDE + c] = f.y + bias;
                    } else {
                        kT[ct * KT_STRIDE + t0] = f.x + bias;
                        kT[ct * KT_STRIDE + t0 + 1] = f.y + bias;
                    }
                }
            }
        }
        // ---- QKV pass 1: cols [384,768) = k[128..255], v[0..255]
        {
            gemm16<3, 8>(hT + half16, g_WqkvT + 384 + ct, 768, 256, acc);
#pragma unroll
            for (int j = 0; j < 3; ++j) {
                const int c = 384 + ct + j * 128;
                const float bias = bqkv[c];
#pragma unroll
                for (int t2 = 0; t2 < 8; ++t2) {
                    float2 f = unpack2(acc[t2 * 3 + j]);
                    const int t0 = half16 + 2 * t2;
                    if (j == 0) {
                        const int d = 128 + ct;
                        kT[d * KT_STRIDE + t0] = f.x + bias;
                        kT[d * KT_STRIDE + t0 + 1] = f.y + bias;
                    } else {
                        const int cc = c - 512;
                        vs[t0 * QS_STRIDE + cc] = f.x + bias;
                        vs[(t0 + 1) * QS_STRIDE + cc] = f.y + bias;
                    }
                }
            }
        }
        __syncthreads();

        // ---- Attention: warp = head. Banded mask |i-j|<=1.
        {
            const int h = wid;
            float kreg[32];
#pragma unroll
            for (int d = 0; d < 32; ++d)
                kreg[d] = kT[(h * 32 + d) * KT_STRIDE + lane];
            const float SC = 0.17677669529663689f;  // 1/sqrt(32)
            for (int i = 0; i < 32; ++i) {
                const float4* qrow = (const float4*)(qs + i * QS_STRIDE + h * 32);
                float s = 0.f;
#pragma unroll
                for (int d4 = 0; d4 < 8; ++d4) {
                    float4 q = qrow[d4];
                    s = fmaf(q.x, kreg[4 * d4 + 0], s);
                    s = fmaf(q.y, kreg[4 * d4 + 1], s);
                    s = fmaf(q.z, kreg[4 * d4 + 2], s);
                    s = fmaf(q.w, kreg[4 * d4 + 3], s);
                }
                s *= SC;
                int dj = lane - i;
                if (dj < 0) dj = -dj;
                if (dj > 1) s -= 1e9f;
                float m = s;
#pragma unroll
                for (int off = 16; off; off >>= 1)
                    m = fmaxf(m, __shfl_xor_sync(0xffffffffu, m, off));
                const float e = expf(s - m);
                float sum = e;
#pragma unroll
                for (int off = 16; off; off >>= 1)
                    sum += __shfl_xor_sync(0xffffffffu, sum, off);
                const float w = e / sum;
                float o = 0.f;
                const int j0 = (i > 0) ? i - 1 : 0;
                const int j1 = (i < 31) ? i + 1 : 31;
                for (int j = j0; j <= j1; ++j) {
                    const float wj = __shfl_sync(0xffffffffu, w, j);
                    o = fmaf(wj, vs[j * QS_STRIDE + h * 32 + lane], o);
                }
                hT[(h * 32 + lane) * AT_STRIDE + i] = o;  // oT, k-major
            }
        }
        __syncthreads();

        // ---- x += o @ Wo^T + bo   (Ct=2)
        {
            gemm16<2, 8>(hT + half16, g_WoT + ct, 256, 256, acc);
#pragma unroll
            for (int j = 0; j < 2; ++j) {
                const int c = ct + j * 128;
                const float bias = bo[c];
#pragma unroll
                for (int t2 = 0; t2 < 8; ++t2) {
                    float2 f = unpack2(acc[t2 * 2 + j]);
                    const int t0 = half16 + 2 * t2;
                    xs[t0 * XS_STRIDE + c] += f.x + bias;
                    xs[(t0 + 1) * XS_STRIDE + c] += f.y + bias;
                }
            }
        }
        __syncthreads();

        // ---- LN2 -> hT
        layer_norm_block(xs, ln2g, ln2b, hT, red, red2, lane, wid);

        // ---- FFN1: u = relu(h2 @ W1 + b1), 2 passes x Ct=4
        for (int pass = 0; pass < 2; ++pass) {
            gemm16<4, 4>(hT + half16, W1 + pass * 512 + ct, 1024, 256, acc);
#pragma unroll
            for (int j = 0; j < 4; ++j) {
                const int f = pass * 512 + ct + j * 128;
                const float bias = b1[f];
#pragma unroll
                for (int t2 = 0; t2 < 8; ++t2) {
                    float2 v = unpack2(acc[t2 * 4 + j]);
                    const int t0 = half16 + 2 * t2;
                    float2 r = make_float2(fmaxf(v.x + bias, 0.f),
                                           fmaxf(v.y + bias, 0.f));
                    *(float2*)(uT + f * AT_STRIDE + t0) = r;
                }
            }
        }
        __syncthreads();

        // ---- FFN2: x += u @ W2 + b2   (Ct=2, K=1024)
        {
            gemm16<2, 8>(uT + half16, W2 + ct, 256, 1024, acc);
#pragma unroll
            for (int j = 0; j < 2; ++j) {
                const int c = ct + j * 128;
                const float bias = b2[c];
#pragma unroll
                for (int t2 = 0; t2 < 8; ++t2) {
                    float2 f = unpack2(acc[t2 * 2 + j]);
                    const int t0 = half16 + 2 * t2;
                    xs[t0 * XS_STRIDE + c] += f.x + bias;
                    xs[(t0 + 1) * XS_STRIDE + c] += f.y + bias;
                }
            }
        }
        __syncthreads();
    }

    for (int i = tid; i < 8192; i += 256)
        gx[i] = xs[(i >> 8) * XS_STRIDE + (i & 255)];
}

// ---------------------------------------------------------------------------
// Tokenizer: x[b][n][e] = obs[b,:] @ emb_W[n] + emb_b[n] + pos[n]
// ---------------------------------------------------------------------------
__global__ void __launch_bounds__(256)
bt_tokenize(const float* __restrict__ obs, const float* __restrict__ embW,
            const float* __restrict__ embB, const float* __restrict__ pos,
            float* __restrict__ out) {
    __shared__ float obs_s[32 * 128];
    const int n = blockIdx.x;
    const int b0 = blockIdx.y * 32;
    const int tid = threadIdx.x;

    const float* src = obs + b0 * 128;
    for (int i = tid; i < 4096; i += 256) obs_s[i] = src[i];
    __syncthreads();

    const int e = tid;
    float acc[32];
#pragma unroll
    for (int bb = 0; bb < 32; ++bb) acc[bb] = 0.f;
    const float* wb = embW + n * 32768 + e;
    for (int d0 = 0; d0 < 128; d0 += 16) {
        float w[16];
#pragma unroll
        for (int dd = 0; dd < 16; ++dd) w[dd] = wb[(d0 + dd) * 256];
#pragma unroll
        for (int bb = 0; bb < 32; ++bb) {
            const float4* orow = (const float4*)(obs_s + bb * 128 + d0);
            float4 o0 = orow[0], o1 = orow[1], o2 = orow[2], o3 = orow[3];
            float a = acc[bb];
            a = fmaf(o0.x, w[0], a);  a = fmaf(o0.y, w[1], a);
            a = fmaf(o0.z, w[2], a);  a = fmaf(o0.w, w[3], a);
            a = fmaf(o1.x, w[4], a);  a = fmaf(o1.y, w[5], a);
            a = fmaf(o1.z, w[6], a);  a = fmaf(o1.w, w[7], a);
            a = fmaf(o2.x, w[8], a);  a = fmaf(o2.y, w[9], a);
            a = fmaf(o2.z, w[10], a); a = fmaf(o2.w, w[11], a);
            a = fmaf(o3.x, w[12], a); a = fmaf(o3.y, w[13], a);
            a = fmaf(o3.z, w[14], a); a = fmaf(o3.w, w[15], a);
            acc[bb] = a;
        }
    }
    const float add = embB[n * 256 + e] + pos[n * 256 + e];
#pragma unroll
    for (int bb = 0; bb < 32; ++bb)
        out[(b0 + bb) * 8192 + n * 256 + e] = acc[bb] + add;
}

__global__ void bt_transpose_wqkv(const float* __restrict__ src) {
    int idx = blockIdx.x * 256 + threadIdx.x;
    if (idx < 768 * 256) {
        int r = idx >> 8, c = idx & 255;
        g_WqkvT[c * 768 + r] = src[idx];
    }
}
__global__ void bt_transpose_wo(const float* __restrict__ src) {
    int idx = blockIdx.x * 256 + threadIdx.x;
    if (idx < 256 * 256) {
        int r = idx >> 8, c = idx & 255;
        g_WoT[c * 256 + r] = src[idx];
    }
}

extern "C" void kernel_launch(void* const* d_in, const int* in_sizes, int n_in,
                              void* d_out, int out_size) {
    (void)in_sizes; (void)n_in; (void)out_size;
    const float* obs  = (const float*)d_in[0];
    const float* embW = (const float*)d_in[1];
    const float* embB = (const float*)d_in[2];
    const float* pos  = (const float*)d_in[3];
    const float* Wqkv = (const float*)d_in[4];
    const float* bqkv = (const float*)d_in[5];
    const float* Wo   = (const float*)d_in[6];
    const float* bo   = (const float*)d_in[7];
    const float* ln1g = (const float*)d_in[8];
    const float* ln1b = (const float*)d_in[9];
    const float* ln2g = (const float*)d_in[10];
    const float* ln2b = (const float*)d_in[11];
    const float* W1   = (const float*)d_in[12];
    const float* b1   = (const float*)d_in[13];
    const float* W2   = (const float*)d_in[14];
    const float* b2   = (const float*)d_in[15];
    float* x = (float*)d_out;

    const int SMEM_BYTES = 54816 * 4;  // 219264
    cudaFuncSetAttribute(bt_main, cudaFuncAttributeMaxDynamicSharedMemorySize,
                         SMEM_BYTES);

    bt_transpose_wqkv<<<768, 256>>>(Wqkv);
    bt_transpose_wo<<<256, 256>>>(Wo);
    bt_tokenize<<<dim3(32, 128), 256>>>(obs, embW, embB, pos, x);
    bt_main<<<4096, 256, SMEM_BYTES>>>(x, bqkv, bo, ln1g, ln1b, ln2g, ln2b,
                                       W1, b1, W2, b2);
}

// round 5
// speedup vs baseline: 1.3107x; 1.0000x over previous
#include <cuda_runtime.h>

// ---------------------------------------------------------------------------
// BodyTransformer fused kernel (fp32, f32x2-packed FMA), sm_103a — round 5
// 512 threads/CTA (4 warps/SMSP) for latency hiding; token quarters.
// ---------------------------------------------------------------------------

#define XS_STRIDE 257   // xs[32][257]
#define AT_STRIDE 36    // aT[k][36] (k-major GEMM input, 16B-aligned rows)
#define KT_STRIDE 33    // kT[d][33]
#define QS_STRIDE 264   // qs/vs[32][264]

__device__ float g_WqkvT[256 * 768];   // [k][c]
__device__ float g_WoT[256 * 256];     // [k][c]

static __device__ __forceinline__ void ffma2(unsigned long long& d,
                                             unsigned long long a,
                                             unsigned long long b) {
    asm("fma.rn.f32x2 %0, %1, %2, %0;" : "+l"(d) : "l"(a), "l"(b));
}
static __device__ __forceinline__ unsigned long long pack2(float x) {
    union { unsigned long long u; float2 f; } cv;
    cv.f = make_float2(x, x);
    return cv.u;
}
static __device__ __forceinline__ float2 unpack2(unsigned long long v) {
    union { unsigned long long u; float2 f; } cv;
    cv.u = v;
    return cv.f;
}

// out[t][c_j] = sum_k aT[k][t] * W[k*ldw + j*128], 8 tokens (4 f32x2) x CT cols.
// aT: broadcast LDS.128; weights: lane-coalesced LDG.32, NB-deep k prefetch.
template <int CT, int NB>
static __device__ __forceinline__ void gemm8(const float* __restrict__ aT,
                                             const float* __restrict__ Wc,
                                             int ldw, int K,
                                             unsigned long long* acc) {
#pragma unroll
    for (int p = 0; p < 4 * CT; ++p) acc[p] = 0ULL;
    float cur[NB][CT], nxt[NB][CT];
#pragma unroll
    for (int kk = 0; kk < NB; ++kk)
#pragma unroll
        for (int j = 0; j < CT; ++j) cur[kk][j] = Wc[kk * ldw + j * 128];
    const int nblk = K / NB;
    for (int blk = 0; blk < nblk; ++blk) {
        const int nb = (blk + 1 < nblk) ? blk + 1 : blk;
        const float* wn = Wc + nb * NB * ldw;
#pragma unroll
        for (int kk = 0; kk < NB; ++kk)
#pragma unroll
            for (int j = 0; j < CT; ++j) nxt[kk][j] = wn[kk * ldw + j * 128];
        const float* arow0 = aT + blk * NB * AT_STRIDE;
#pragma unroll
        for (int kk = 0; kk < NB; ++kk) {
            const double2* row = (const double2*)(arow0 + kk * AT_STRIDE);
            double2 a0 = row[0], a1 = row[1];
            unsigned long long av[4];
            av[0] = __double_as_longlong(a0.x); av[1] = __double_as_longlong(a0.y);
            av[2] = __double_as_longlong(a1.x); av[3] = __double_as_longlong(a1.y);
#pragma unroll
            for (int j = 0; j < CT; ++j) {
                const unsigned long long wpk = pack2(cur[kk][j]);
#pragma unroll
                for (int t = 0; t < 4; ++t) ffma2(acc[t * CT + j], av[t], wpk);
            }
        }
#pragma unroll
        for (int kk = 0; kk < NB; ++kk)
#pragma unroll
            for (int j = 0; j < CT; ++j) cur[kk][j] = nxt[kk][j];
    }
}

// LayerNorm xs -> outT (k-major). lane = token, wid (0..15) = 16-col strip.
static __device__ __forceinline__ void layer_norm_block(
    const float* __restrict__ xs, const float* __restrict__ g,
    const float* __restrict__ bb, float* __restrict__ outT,
    float* __restrict__ red, float* __restrict__ red2, int lane, int wid) {
    const float* row = xs + lane * XS_STRIDE + wid * 16;
    float s = 0.f, s2 = 0.f;
#pragma unroll
    for (int i = 0; i < 16; ++i) {
        float v = row[i];
        s += v;
        s2 = fmaf(v, v, s2);
    }
    red[wid * 32 + lane] = s;
    red2[wid * 32 + lane] = s2;
    __syncthreads();
    float t = 0.f, t2 = 0.f;
#pragma unroll
    for (int w = 0; w < 16; ++w) {
        t += red[w * 32 + lane];
        t2 += red2[w * 32 + lane];
    }
    const float mean = t * 0.00390625f;
    const float var = t2 * 0.00390625f - mean * mean;
    const float rstd = rsqrtf(var + 1e-5f);
#pragma unroll
    for (int i = 0; i < 16; ++i) {
        const int c = wid * 16 + i;
        outT[c * AT_STRIDE + lane] = (row[i] - mean) * rstd * g[c] + bb[c];
    }
    __syncthreads();
}

// ---------------------------------------------------------------------------
// Main fused kernel: one CTA per batch item, 6 layers in shared memory.
// smem: xs(8224) | red(512) | red2(512) | S(46080) = 55328 floats = 221312 B
// S: hT[256][36] @0 ; qs[32][264] @9216 ; kT[256][33] @17664 ; vs[32][264] @26112
//    uT[1024][36] @9216 (FFN phase, overlaps qs/kT/vs)
// ---------------------------------------------------------------------------
__global__ void __launch_bounds__(512, 1)
bt_main(float* __restrict__ x,
        const float* __restrict__ bqkv, const float* __restrict__ bo,
        const float* __restrict__ ln1g, const float* __restrict__ ln1b,
        const float* __restrict__ ln2g, const float* __restrict__ ln2b,
        const float* __restrict__ W1, const float* __restrict__ b1,
        const float* __restrict__ W2, const float* __restrict__ b2) {
    extern __shared__ float sm[];
    float* xs = sm;                 // 32*257
    float* red = sm + 8224;         // 512
    float* red2 = sm + 8736;        // 512
    float* S = sm + 9248;
    float* hT = S;                  // 256*36 (also oT / h2T)
    float* qs = S + 9216;           // 32*264
    float* kT = S + 17664;          // 256*33
    float* vs = S + 26112;          // 32*264
    float* uT = S + 9216;           // 1024*36 (FFN phase)

    const int tid = threadIdx.x;
    const int lane = tid & 31;
    const int wid = tid >> 5;
    const int ct = tid & 127;             // column-thread within quarter
    const int q8 = (tid >> 7) << 3;       // 0,8,16,24: token-quarter base
    const int b = blockIdx.x;
    float* gx = x + b * 8192;

    for (int i = tid; i < 8192; i += 512)
        xs[(i >> 8) * XS_STRIDE + (i & 255)] = gx[i];
    __syncthreads();

    unsigned long long acc[16];

    for (int layer = 0; layer < 6; ++layer) {
        // ---- LN1 -> hT
        layer_norm_block(xs, ln1g, ln1b, hT, red, red2, lane, wid);

        // ---- QKV pass 0: cols [0,384) = q[0..255], k[0..127]
        {
            gemm8<3, 8>(hT + q8, g_WqkvT + ct, 768, 256, acc);
#pragma unroll
            for (int j = 0; j < 3; ++j) {
                const int c = ct + j * 128;
                const float bias = bqkv[c];
#pragma unroll
                for (int t2 = 0; t2 < 4; ++t2) {
                    float2 f = unpack2(acc[t2 * 3 + j]);
                    const int t0 = q8 + 2 * t2;
                    if (j < 2) {
                        qs[t0 * QS_STRIDE + c] = f.x + bias;
                        qs[(t0 + 1) * QS_STRIDE + c] = f.y + bias;
                    } else {
                        kT[ct * KT_STRIDE + t0] = f.x + bias;
                        kT[ct * KT_STRIDE + t0 + 1] = f.y + bias;
                    }
                }
            }
        }
        // ---- QKV pass 1: cols [384,768) = k[128..255], v[0..255]
        {
            gemm8<3, 8>(hT + q8, g_WqkvT + 384 + ct, 768, 256, acc);
#pragma unroll
            for (int j = 0; j < 3; ++j) {
                const int c = 384 + ct + j * 128;
                const float bias = bqkv[c];
#pragma unroll
                for (int t2 = 0; t2 < 4; ++t2) {
                    float2 f = unpack2(acc[t2 * 3 + j]);
                    const int t0 = q8 + 2 * t2;
                    if (j == 0) {
                        const int d = 128 + ct;
                        kT[d * KT_STRIDE + t0] = f.x + bias;
                        kT[d * KT_STRIDE + t0 + 1] = f.y + bias;
                    } else {
                        const int cc = c - 512;
                        vs[t0 * QS_STRIDE + cc] = f.x + bias;
                        vs[(t0 + 1) * QS_STRIDE + cc] = f.y + bias;
                    }
                }
            }
        }
        __syncthreads();

        // ---- Attention: 2 warps per head (i-halves). Banded mask |i-j|<=1.
        {
            const int h = wid & 7;
            const int ibase = (wid >> 3) * 16;
            float kreg[32];
#pragma unroll
            for (int d = 0; d < 32; ++d)
                kreg[d] = kT[(h * 32 + d) * KT_STRIDE + lane];
            const float SC = 0.17677669529663689f;  // 1/sqrt(32)
            for (int ii = 0; ii < 16; ++ii) {
                const int i = ibase + ii;
                const float4* qrow = (const float4*)(qs + i * QS_STRIDE + h * 32);
                float s = 0.f;
#pragma unroll
                for (int d4 = 0; d4 < 8; ++d4) {
                    float4 q = qrow[d4];
                    s = fmaf(q.x, kreg[4 * d4 + 0], s);
                    s = fmaf(q.y, kreg[4 * d4 + 1], s);
                    s = fmaf(q.z, kreg[4 * d4 + 2], s);
                    s = fmaf(q.w, kreg[4 * d4 + 3], s);
                }
                s *= SC;
                int dj = lane - i;
                if (dj < 0) dj = -dj;
                if (dj > 1) s -= 1e9f;
                float m = s;
#pragma unroll
                for (int off = 16; off; off >>= 1)
                    m = fmaxf(m, __shfl_xor_sync(0xffffffffu, m, off));
                const float e = expf(s - m);
                float sum = e;
#pragma unroll
                for (int off = 16; off; off >>= 1)
                    sum += __shfl_xor_sync(0xffffffffu, sum, off);
                const float w = e / sum;
                float o = 0.f;
                const int j0 = (i > 0) ? i - 1 : 0;
                const int j1 = (i < 31) ? i + 1 : 31;
                for (int j = j0; j <= j1; ++j) {
                    const float wj = __shfl_sync(0xffffffffu, w, j);
                    o = fmaf(wj, vs[j * QS_STRIDE + h * 32 + lane], o);
                }
                hT[(h * 32 + lane) * AT_STRIDE + i] = o;  // oT, k-major
            }
        }
        __syncthreads();

        // ---- x += o @ Wo^T + bo   (Ct=2)
        {
            gemm8<2, 8>(hT + q8, g_WoT + ct, 256, 256, acc);
#pragma unroll
            for (int j = 0; j < 2; ++j) {
                const int c = ct + j * 128;
                const float bias = bo[c];
#pragma unroll
                for (int t2 = 0; t2 < 4; ++t2) {
                    float2 f = unpack2(acc[t2 * 2 + j]);
                    const int t0 = q8 + 2 * t2;
                    xs[t0 * XS_STRIDE + c] += f.x + bias;
                    xs[(t0 + 1) * XS_STRIDE + c] += f.y + bias;
                }
            }
        }
        __syncthreads();

        // ---- LN2 -> hT
        layer_norm_block(xs, ln2g, ln2b, hT, red, red2, lane, wid);

        // ---- FFN1: u = relu(h2 @ W1 + b1), 2 passes x Ct=4
        for (int pass = 0; pass < 2; ++pass) {
            gemm8<4, 8>(hT + q8, W1 + pass * 512 + ct, 1024, 256, acc);
#pragma unroll
            for (int j = 0; j < 4; ++j) {
                const int f = pass * 512 + ct + j * 128;
                const float bias = b1[f];
#pragma unroll
                for (int t2 = 0; t2 < 4; ++t2) {
                    float2 v = unpack2(acc[t2 * 4 + j]);
                    const int t0 = q8 + 2 * t2;
                    float2 r = make_float2(fmaxf(v.x + bias, 0.f),
                                           fmaxf(v.y + bias, 0.f));
                    *(float2*)(uT + f * AT_STRIDE + t0) = r;
                }
            }
        }
        __syncthreads();

        // ---- FFN2: x += u @ W2 + b2   (Ct=2, K=1024)
        {
            gemm8<2, 8>(uT + q8, W2 + ct, 256, 1024, acc);
#pragma unroll
            for (int j = 0; j < 2; ++j) {
                const int c = ct + j * 128;
                const float bias = b2[c];
#pragma unroll
                for (int t2 = 0; t2 < 4; ++t2) {
                    float2 f = unpack2(acc[t2 * 2 + j]);
                    const int t0 = q8 + 2 * t2;
                    xs[t0 * XS_STRIDE + c] += f.x + bias;
                    xs[(t0 + 1) * XS_STRIDE + c] += f.y + bias;
                }
            }
        }
        __syncthreads();
    }

    for (int i = tid; i < 8192; i += 512)
        gx[i] = xs[(i >> 8) * XS_STRIDE + (i & 255)];
}

// ---------------------------------------------------------------------------
// Tokenizer: x[b][n][e] = obs[b,:] @ emb_W[n] + emb_b[n] + pos[n]
// ---------------------------------------------------------------------------
__global__ void __launch_bounds__(256)
bt_tokenize(const float* __restrict__ obs, const float* __restrict__ embW,
            const float* __restrict__ embB, const float* __restrict__ pos,
            float* __restrict__ out) {
    __shared__ float obs_s[32 * 128];
    const int n = blockIdx.x;
    const int b0 = blockIdx.y * 32;
    const int tid = threadIdx.x;

    const float* src = obs + b0 * 128;
    for (int i = tid; i < 4096; i += 256) obs_s[i] = src[i];
    __syncthreads();

    const int e = tid;
    float acc[32];
#pragma unroll
    for (int bb = 0; bb < 32; ++bb) acc[bb] = 0.f;
    const float* wb = embW + n * 32768 + e;
    for (int d0 = 0; d0 < 128; d0 += 16) {
        float w[16];
#pragma unroll
        for (int dd = 0; dd < 16; ++dd) w[dd] = wb[(d0 + dd) * 256];
#pragma unroll
        for (int bb = 0; bb < 32; ++bb) {
            const float4* orow = (const float4*)(obs_s + bb * 128 + d0);
            float4 o0 = orow[0], o1 = orow[1], o2 = orow[2], o3 = orow[3];
            float a = acc[bb];
            a = fmaf(o0.x, w[0], a);  a = fmaf(o0.y, w[1], a);
            a = fmaf(o0.z, w[2], a);  a = fmaf(o0.w, w[3], a);
            a = fmaf(o1.x, w[4], a);  a = fmaf(o1.y, w[5], a);
            a = fmaf(o1.z, w[6], a);  a = fmaf(o1.w, w[7], a);
            a = fmaf(o2.x, w[8], a);  a = fmaf(o2.y, w[9], a);
            a = fmaf(o2.z, w[10], a); a = fmaf(o2.w, w[11], a);
            a = fmaf(o3.x, w[12], a); a = fmaf(o3.y, w[13], a);
            a = fmaf(o3.z, w[14], a); a = fmaf(o3.w, w[15], a);
            acc[bb] = a;
        }
    }
    const float add = embB[n * 256 + e] + pos[n * 256 + e];
#pragma unroll
    for (int bb = 0; bb < 32; ++bb)
        out[(b0 + bb) * 8192 + n * 256 + e] = acc[bb] + add;
}

__global__ void bt_transpose_wqkv(const float* __restrict__ src) {
    int idx = blockIdx.x * 256 + threadIdx.x;
    if (idx < 768 * 256) {
        int r = idx >> 8, c = idx & 255;
        g_WqkvT[c * 768 + r] = src[idx];
    }
}
__global__ void bt_transpose_wo(const float* __restrict__ src) {
    int idx = blockIdx.x * 256 + threadIdx.x;
    if (idx < 256 * 256) {
        int r = idx >> 8, c = idx & 255;
        g_WoT[c * 256 + r] = src[idx];
    }
}

extern "C" void kernel_launch(void* const* d_in, const int* in_sizes, int n_in,
                              void* d_out, int out_size) {
    (void)in_sizes; (void)n_in; (void)out_size;
    const float* obs  = (const float*)d_in[0];
    const float* embW = (const float*)d_in[1];
    const float* embB = (const float*)d_in[2];
    const float* pos  = (const float*)d_in[3];
    const float* Wqkv = (const float*)d_in[4];
    const float* bqkv = (const float*)d_in[5];
    const float* Wo   = (const float*)d_in[6];
    const float* bo   = (const float*)d_in[7];
    const float* ln1g = (const float*)d_in[8];
    const float* ln1b = (const float*)d_in[9];
    const float* ln2g = (const float*)d_in[10];
    const float* ln2b = (const float*)d_in[11];
    const float* W1   = (const float*)d_in[12];
    const float* b1   = (const float*)d_in[13];
    const float* W2   = (const float*)d_in[14];
    const float* b2   = (const float*)d_in[15];
    float* x = (float*)d_out;

    const int SMEM_BYTES = 55328 * 4;  // 221312
    cudaFuncSetAttribute(bt_main, cudaFuncAttributeMaxDynamicSharedMemorySize,
                         SMEM_BYTES);

    bt_transpose_wqkv<<<768, 256>>>(Wqkv);
    bt_transpose_wo<<<256, 256>>>(Wo);
    bt_tokenize<<<dim3(32, 128), 256>>>(obs, embW, embB, pos, x);
    bt_main<<<4096, 512, SMEM_BYTES>>>(x, bqkv, bo, ln1g, ln1b, ln2g, ln2b,
                                       W1, b1, W2, b2);
}

// round 6
// speedup vs baseline: 1.3132x; 1.0019x over previous
#include <cuda_runtime.h>

// ---------------------------------------------------------------------------
// BodyTransformer fused kernel (fp32, f32x2-packed FMA), sm_103a — round 5
// 512 threads/CTA (4 warps/SMSP) for latency hiding; token quarters.
// ---------------------------------------------------------------------------

#define XS_STRIDE 257   // xs[32][257]
#define AT_STRIDE 36    // aT[k][36] (k-major GEMM input, 16B-aligned rows)
#define KT_STRIDE 33    // kT[d][33]
#define QS_STRIDE 264   // qs/vs[32][264]

__device__ float g_WqkvT[256 * 768];   // [k][c]
__device__ float g_WoT[256 * 256];     // [k][c]

static __device__ __forceinline__ void ffma2(unsigned long long& d,
                                             unsigned long long a,
                                             unsigned long long b) {
    asm("fma.rn.f32x2 %0, %1, %2, %0;" : "+l"(d) : "l"(a), "l"(b));
}
static __device__ __forceinline__ unsigned long long pack2(float x) {
    union { unsigned long long u; float2 f; } cv;
    cv.f = make_float2(x, x);
    return cv.u;
}
static __device__ __forceinline__ float2 unpack2(unsigned long long v) {
    union { unsigned long long u; float2 f; } cv;
    cv.u = v;
    return cv.f;
}

// out[t][c_j] = sum_k aT[k][t] * W[k*ldw + j*128], 8 tokens (4 f32x2) x CT cols.
// aT: broadcast LDS.128; weights: lane-coalesced LDG.32, NB-deep k prefetch.
template <int CT, int NB>
static __device__ __forceinline__ void gemm8(const float* __restrict__ aT,
                                             const float* __restrict__ Wc,
                                             int ldw, int K,
                                             unsigned long long* acc) {
#pragma unroll
    for (int p = 0; p < 4 * CT; ++p) acc[p] = 0ULL;
    float cur[NB][CT], nxt[NB][CT];
#pragma unroll
    for (int kk = 0; kk < NB; ++kk)
#pragma unroll
        for (int j = 0; j < CT; ++j) cur[kk][j] = Wc[kk * ldw + j * 128];
    const int nblk = K / NB;
    for (int blk = 0; blk < nblk; ++blk) {
        const int nb = (blk + 1 < nblk) ? blk + 1 : blk;
        const float* wn = Wc + nb * NB * ldw;
#pragma unroll
        for (int kk = 0; kk < NB; ++kk)
#pragma unroll
            for (int j = 0; j < CT; ++j) nxt[kk][j] = wn[kk * ldw + j * 128];
        const float* arow0 = aT + blk * NB * AT_STRIDE;
#pragma unroll
        for (int kk = 0; kk < NB; ++kk) {
            const double2* row = (const double2*)(arow0 + kk * AT_STRIDE);
            double2 a0 = row[0], a1 = row[1];
            unsigned long long av[4];
            av[0] = __double_as_longlong(a0.x); av[1] = __double_as_longlong(a0.y);
            av[2] = __double_as_longlong(a1.x); av[3] = __double_as_longlong(a1.y);
#pragma unroll
            for (int j = 0; j < CT; ++j) {
                const unsigned long long wpk = pack2(cur[kk][j]);
#pragma unroll
                for (int t = 0; t < 4; ++t) ffma2(acc[t * CT + j], av[t], wpk);
            }
        }
#pragma unroll
        for (int kk = 0; kk < NB; ++kk)
#pragma unroll
            for (int j = 0; j < CT; ++j) cur[kk][j] = nxt[kk][j];
    }
}

// LayerNorm xs -> outT (k-major). lane = token, wid (0..15) = 16-col strip.
static __device__ __forceinline__ void layer_norm_block(
    const float* __restrict__ xs, const float* __restrict__ g,
    const float* __restrict__ bb, float* __restrict__ outT,
    float* __restrict__ red, float* __restrict__ red2, int lane, int wid) {
    const float* row = xs + lane * XS_STRIDE + wid * 16;
    float s = 0.f, s2 = 0.f;
#pragma unroll
    for (int i = 0; i < 16; ++i) {
        float v = row[i];
        s += v;
        s2 = fmaf(v, v, s2);
    }
    red[wid * 32 + lane] = s;
    red2[wid * 32 + lane] = s2;
    __syncthreads();
    float t = 0.f, t2 = 0.f;
#pragma unroll
    for (int w = 0; w < 16; ++w) {
        t += red[w * 32 + lane];
        t2 += red2[w * 32 + lane];
    }
    const float mean = t * 0.00390625f;
    const float var = t2 * 0.00390625f - mean * mean;
    const float rstd = rsqrtf(var + 1e-5f);
#pragma unroll
    for (int i = 0; i < 16; ++i) {
        const int c = wid * 16 + i;
        outT[c * AT_STRIDE + lane] = (row[i] - mean) * rstd * g[c] + bb[c];
    }
    __syncthreads();
}

// ---------------------------------------------------------------------------
// Main fused kernel: one CTA per batch item, 6 layers in shared memory.
// smem: xs(8224) | red(512) | red2(512) | S(46080) = 55328 floats = 221312 B
// S: hT[256][36] @0 ; qs[32][264] @9216 ; kT[256][33] @17664 ; vs[32][264] @26112
//    uT[1024][36] @9216 (FFN phase, overlaps qs/kT/vs)
// ---------------------------------------------------------------------------
__global__ void __launch_bounds__(512, 1)
bt_main(float* __restrict__ x,
        const float* __restrict__ bqkv, const float* __restrict__ bo,
        const float* __restrict__ ln1g, const float* __restrict__ ln1b,
        const float* __restrict__ ln2g, const float* __restrict__ ln2b,
        const float* __restrict__ W1, const float* __restrict__ b1,
        const float* __restrict__ W2, const float* __restrict__ b2) {
    extern __shared__ float sm[];
    float* xs = sm;                 // 32*257
    float* red = sm + 8224;         // 512
    float* red2 = sm + 8736;        // 512
    float* S = sm + 9248;
    float* hT = S;                  // 256*36 (also oT / h2T)
    float* qs = S + 9216;           // 32*264
    float* kT = S + 17664;          // 256*33
    float* vs = S + 26112;          // 32*264
    float* uT = S + 9216;           // 1024*36 (FFN phase)

    const int tid = threadIdx.x;
    const int lane = tid & 31;
    const int wid = tid >> 5;
    const int ct = tid & 127;             // column-thread within quarter
    const int q8 = (tid >> 7) << 3;       // 0,8,16,24: token-quarter base
    const int b = blockIdx.x;
    float* gx = x + b * 8192;

    for (int i = tid; i < 8192; i += 512)
        xs[(i >> 8) * XS_STRIDE + (i & 255)] = gx[i];
    __syncthreads();

    unsigned long long acc[16];

    for (int layer = 0; layer < 6; ++layer) {
        // ---- LN1 -> hT
        layer_norm_block(xs, ln1g, ln1b, hT, red, red2, lane, wid);

        // ---- QKV pass 0: cols [0,384) = q[0..255], k[0..127]
        {
            gemm8<3, 8>(hT + q8, g_WqkvT + ct, 768, 256, acc);
#pragma unroll
            for (int j = 0; j < 3; ++j) {
                const int c = ct + j * 128;
                const float bias = bqkv[c];
#pragma unroll
                for (int t2 = 0; t2 < 4; ++t2) {
                    float2 f = unpack2(acc[t2 * 3 + j]);
                    const int t0 = q8 + 2 * t2;
                    if (j < 2) {
                        qs[t0 * QS_STRIDE + c] = f.x + bias;
                        qs[(t0 + 1) * QS_STRIDE + c] = f.y + bias;
                    } else {
                        kT[ct * KT_STRIDE + t0] = f.x + bias;
                        kT[ct * KT_STRIDE + t0 + 1] = f.y + bias;
                    }
                }
            }
        }
        // ---- QKV pass 1: cols [384,768) = k[128..255], v[0..255]
        {
            gemm8<3, 8>(hT + q8, g_WqkvT + 384 + ct, 768, 256, acc);
#pragma unroll
            for (int j = 0; j < 3; ++j) {
                const int c = 384 + ct + j * 128;
                const float bias = bqkv[c];
#pragma unroll
                for (int t2 = 0; t2 < 4; ++t2) {
                    float2 f = unpack2(acc[t2 * 3 + j]);
                    const int t0 = q8 + 2 * t2;
                    if (j == 0) {
                        const int d = 128 + ct;
                        kT[d * KT_STRIDE + t0] = f.x + bias;
                        kT[d * KT_STRIDE + t0 + 1] = f.y + bias;
                    } else {
                        const int cc = c - 512;
                        vs[t0 * QS_STRIDE + cc] = f.x + bias;
                        vs[(t0 + 1) * QS_STRIDE + cc] = f.y + bias;
                    }
                }
            }
        }
        __syncthreads();

        // ---- Attention: 2 warps per head (i-halves). Banded mask |i-j|<=1.
        {
            const int h = wid & 7;
            const int ibase = (wid >> 3) * 16;
            float kreg[32];
#pragma unroll
            for (int d = 0; d < 32; ++d)
                kreg[d] = kT[(h * 32 + d) * KT_STRIDE + lane];
            const float SC = 0.17677669529663689f;  // 1/sqrt(32)
            for (int ii = 0; ii < 16; ++ii) {
                const int i = ibase + ii;
                const float4* qrow = (const float4*)(qs + i * QS_STRIDE + h * 32);
                float s = 0.f;
#pragma unroll
                for (int d4 = 0; d4 < 8; ++d4) {
                    float4 q = qrow[d4];
                    s = fmaf(q.x, kreg[4 * d4 + 0], s);
                    s = fmaf(q.y, kreg[4 * d4 + 1], s);
                    s = fmaf(q.z, kreg[4 * d4 + 2], s);
                    s = fmaf(q.w, kreg[4 * d4 + 3], s);
                }
                s *= SC;
                int dj = lane - i;
                if (dj < 0) dj = -dj;
                if (dj > 1) s -= 1e9f;
                float m = s;
#pragma unroll
                for (int off = 16; off; off >>= 1)
                    m = fmaxf(m, __shfl_xor_sync(0xffffffffu, m, off));
                const float e = expf(s - m);
                float sum = e;
#pragma unroll
                for (int off = 16; off; off >>= 1)
                    sum += __shfl_xor_sync(0xffffffffu, sum, off);
                const float w = e / sum;
                float o = 0.f;
                const int j0 = (i > 0) ? i - 1 : 0;
                const int j1 = (i < 31) ? i + 1 : 31;
                for (int j = j0; j <= j1; ++j) {
                    const float wj = __shfl_sync(0xffffffffu, w, j);
                    o = fmaf(wj, vs[j * QS_STRIDE + h * 32 + lane], o);
                }
                hT[(h * 32 + lane) * AT_STRIDE + i] = o;  // oT, k-major
            }
        }
        __syncthreads();

        // ---- x += o @ Wo^T + bo   (Ct=2)
        {
            gemm8<2, 8>(hT + q8, g_WoT + ct, 256, 256, acc);
#pragma unroll
            for (int j = 0; j < 2; ++j) {
                const int c = ct + j * 128;
                const float bias = bo[c];
#pragma unroll
                for (int t2 = 0; t2 < 4; ++t2) {
                    float2 f = unpack2(acc[t2 * 2 + j]);
                    const int t0 = q8 + 2 * t2;
                    xs[t0 * XS_STRIDE + c] += f.x + bias;
                    xs[(t0 + 1) * XS_STRIDE + c] += f.y + bias;
                }
            }
        }
        __syncthreads();

        // ---- LN2 -> hT
        layer_norm_block(xs, ln2g, ln2b, hT, red, red2, lane, wid);

        // ---- FFN1: u = relu(h2 @ W1 + b1), 2 passes x Ct=4
        for (int pass = 0; pass < 2; ++pass) {
            gemm8<4, 8>(hT + q8, W1 + pass * 512 + ct, 1024, 256, acc);
#pragma unroll
            for (int j = 0; j < 4; ++j) {
                const int f = pass * 512 + ct + j * 128;
                const float bias = b1[f];
#pragma unroll
                for (int t2 = 0; t2 < 4; ++t2) {
                    float2 v = unpack2(acc[t2 * 4 + j]);
                    const int t0 = q8 + 2 * t2;
                    float2 r = make_float2(fmaxf(v.x + bias, 0.f),
                                           fmaxf(v.y + bias, 0.f));
                    *(float2*)(uT + f * AT_STRIDE + t0) = r;
                }
            }
        }
        __syncthreads();

        // ---- FFN2: x += u @ W2 + b2   (Ct=2, K=1024)
        {
            gemm8<2, 8>(uT + q8, W2 + ct, 256, 1024, acc);
#pragma unroll
            for (int j = 0; j < 2; ++j) {
                const int c = ct + j * 128;
                const float bias = b2[c];
#pragma unroll
                for (int t2 = 0; t2 < 4; ++t2) {
                    float2 f = unpack2(acc[t2 * 2 + j]);
                    const int t0 = q8 + 2 * t2;
                    xs[t0 * XS_STRIDE + c] += f.x + bias;
                    xs[(t0 + 1) * XS_STRIDE + c] += f.y + bias;
                }
            }
        }
        __syncthreads();
    }

    for (int i = tid; i < 8192; i += 512)
        gx[i] = xs[(i >> 8) * XS_STRIDE + (i & 255)];
}

// ---------------------------------------------------------------------------
// Tokenizer: x[b][n][e] = obs[b,:] @ emb_W[n] + emb_b[n] + pos[n]
// ---------------------------------------------------------------------------
__global__ void __launch_bounds__(256)
bt_tokenize(const float* __restrict__ obs, const float* __restrict__ embW,
            const float* __restrict__ embB, const float* __restrict__ pos,
            float* __restrict__ out) {
    __shared__ float obs_s[32 * 128];
    const int n = blockIdx.x;
    const int b0 = blockIdx.y * 32;
    const int tid = threadIdx.x;

    const float* src = obs + b0 * 128;
    for (int i = tid; i < 4096; i += 256) obs_s[i] = src[i];
    __syncthreads();

    const int e = tid;
    float acc[32];
#pragma unroll
    for (int bb = 0; bb < 32; ++bb) acc[bb] = 0.f;
    const float* wb = embW + n * 32768 + e;
    for (int d0 = 0; d0 < 128; d0 += 16) {
        float w[16];
#pragma unroll
        for (int dd = 0; dd < 16; ++dd) w[dd] = wb[(d0 + dd) * 256];
#pragma unroll
        for (int bb = 0; bb < 32; ++bb) {
            const float4* orow = (const float4*)(obs_s + bb * 128 + d0);
            float4 o0 = orow[0], o1 = orow[1], o2 = orow[2], o3 = orow[3];
            float a = acc[bb];
            a = fmaf(o0.x, w[0], a);  a = fmaf(o0.y, w[1], a);
            a = fmaf(o0.z, w[2], a);  a = fmaf(o0.w, w[3], a);
            a = fmaf(o1.x, w[4], a);  a = fmaf(o1.y, w[5], a);
            a = fmaf(o1.z, w[6], a);  a = fmaf(o1.w, w[7], a);
            a = fmaf(o2.x, w[8], a);  a = fmaf(o2.y, w[9], a);
            a = fmaf(o2.z, w[10], a); a = fmaf(o2.w, w[11], a);
            a = fmaf(o3.x, w[12], a); a = fmaf(o3.y, w[13], a);
            a = fmaf(o3.z, w[14], a); a = fmaf(o3.w, w[15], a);
            acc[bb] = a;
        }
    }
    const float add = embB[n * 256 + e] + pos[n * 256 + e];
#pragma unroll
    for (int bb = 0; bb < 32; ++bb)
        out[(b0 + bb) * 8192 + n * 256 + e] = acc[bb] + add;
}

__global__ void bt_transpose_wqkv(const float* __restrict__ src) {
    int idx = blockIdx.x * 256 + threadIdx.x;
    if (idx < 768 * 256) {
        int r = idx >> 8, c = idx & 255;
        g_WqkvT[c * 768 + r] = src[idx];
    }
}
__global__ void bt_transpose_wo(const float* __restrict__ src) {
    int idx = blockIdx.x * 256 + threadIdx.x;
    if (idx < 256 * 256) {
        int r = idx >> 8, c = idx & 255;
        g_WoT[c * 256 + r] = src[idx];
    }
}

extern "C" void kernel_launch(void* const* d_in, const int* in_sizes, int n_in,
                              void* d_out, int out_size) {
    (void)in_sizes; (void)n_in; (void)out_size;
    const float* obs  = (const float*)d_in[0];
    const float* embW = (const float*)d_in[1];
    const float* embB = (const float*)d_in[2];
    const float* pos  = (const float*)d_in[3];
    const float* Wqkv = (const float*)d_in[4];
    const float* bqkv = (const float*)d_in[5];
    const float* Wo   = (const float*)d_in[6];
    const float* bo   = (const float*)d_in[7];
    const float* ln1g = (const float*)d_in[8];
    const float* ln1b = (const float*)d_in[9];
    const float* ln2g = (const float*)d_in[10];
    const float* ln2b = (const float*)d_in[11];
    const float* W1   = (const float*)d_in[12];
    const float* b1   = (const float*)d_in[13];
    const float* W2   = (const float*)d_in[14];
    const float* b2   = (const float*)d_in[15];
    float* x = (float*)d_out;

    const int SMEM_BYTES = 55328 * 4;  // 221312
    cudaFuncSetAttribute(bt_main, cudaFuncAttributeMaxDynamicSharedMemorySize,
                         SMEM_BYTES);

    bt_transpose_wqkv<<<768, 256>>>(Wqkv);
    bt_transpose_wo<<<256, 256>>>(Wo);
    bt_tokenize<<<dim3(32, 128), 256>>>(obs, embW, embB, pos, x);
    bt_main<<<4096, 512, SMEM_BYTES>>>(x, bqkv, bo, ln1g, ln1b, ln2g, ln2b,
                                       W1, b1, W2, b2);
}

// round 8
// speedup vs baseline: 2.1878x; 1.6660x over previous
#include <cuda_runtime.h>
#include <cuda_bf16.h>
#include <cstdint>

// ---------------------------------------------------------------------------
// BodyTransformer via mma.sync bf16-pair GEMMs (sm_103-safe, no tcgen05)
// M=131072 rows, E=256, H=8, DH=32, F=1024, L=6 (shared weights)
// D = Ah*Bh + Ah*Bl + Al*Bh, fp32 register accumulation.
// ---------------------------------------------------------------------------

#define MM 131072

__device__ __align__(16) __nv_bfloat16 g_h_hi[(size_t)MM * 256];
__device__ __align__(16) __nv_bfloat16 g_h_lo[(size_t)MM * 256];
__device__ __align__(16) float         g_qkv[(size_t)MM * 768];
__device__ __align__(16) __nv_bfloat16 g_o_hi[(size_t)MM * 256];
__device__ __align__(16) __nv_bfloat16 g_o_lo[(size_t)MM * 256];
__device__ __align__(16) __nv_bfloat16 g_u_hi[(size_t)MM * 1024];
__device__ __align__(16) __nv_bfloat16 g_u_lo[(size_t)MM * 1024];
__device__ __align__(16) __nv_bfloat16 g_Bqkv_h[768 * 256], g_Bqkv_l[768 * 256];
__device__ __align__(16) __nv_bfloat16 g_Bo_h[256 * 256],   g_Bo_l[256 * 256];
__device__ __align__(16) __nv_bfloat16 g_B1_h[1024 * 256],  g_B1_l[1024 * 256];
__device__ __align__(16) __nv_bfloat16 g_B2_h[256 * 1024],  g_B2_l[256 * 1024];

static __device__ __forceinline__ uint32_t smem_u32(const void* p) {
    uint32_t a;
    asm("{ .reg .u64 t; cvta.to.shared.u64 t, %1; cvt.u32.u64 %0, t; }"
        : "=r"(a) : "l"(p));
    return a;
}
static __device__ __forceinline__ void ldm4(uint32_t* r, uint32_t addr) {
    asm volatile("ldmatrix.sync.aligned.m8n8.x4.shared.b16 {%0,%1,%2,%3}, [%4];"
                 : "=r"(r[0]), "=r"(r[1]), "=r"(r[2]), "=r"(r[3]) : "r"(addr));
}
static __device__ __forceinline__ void mma_bf16(float* d, const uint32_t* a,
                                                uint32_t b0, uint32_t b1) {
    asm volatile(
        "mma.sync.aligned.m16n8k16.row.col.f32.bf16.bf16.f32 "
        "{%0,%1,%2,%3}, {%4,%5,%6,%7}, {%8,%9}, {%0,%1,%2,%3};"
        : "+f"(d[0]), "+f"(d[1]), "+f"(d[2]), "+f"(d[3])
        : "r"(a[0]), "r"(a[1]), "r"(a[2]), "r"(a[3]), "r"(b0), "r"(b1));
}
static __device__ __forceinline__ void split_pair(float v, __nv_bfloat16& h,
                                                  __nv_bfloat16& l) {
    h = __float2bfloat16(v);
    l = __float2bfloat16(v - __bfloat162float(h));
}

// ---------------------------------------------------------------------------
// GEMM: D[128 x 128] = A_pair[m0..,K] * B_pair[n0..,K]^T (+ epilogue)
// blockIdx.x = N tile (A reuse in L2 across concurrent CTAs), .y = M tile.
// MODE 0: fp32 +bias; 1: relu+bias -> bf16 pair; 2: resid += (+bias)
// smem: sAh|sAl|sBh|sBl each 128 x 72 bf16 (144B rows, conflict-free ldmatrix)
// ---------------------------------------------------------------------------
#define ROWB 144  // 72 bf16
template <int MODE>
static __device__ __forceinline__ void gemm_body(
    const __nv_bfloat16* __restrict__ Ah, const __nv_bfloat16* __restrict__ Al,
    const __nv_bfloat16* __restrict__ Bh, const __nv_bfloat16* __restrict__ Bl,
    const float* __restrict__ bias, float* __restrict__ outF,
    __nv_bfloat16* __restrict__ outPh, __nv_bfloat16* __restrict__ outPl,
    float* __restrict__ resid, int K, int out_ld) {
    extern __shared__ __nv_bfloat16 sm[];
    __nv_bfloat16* sAh = sm;               // 128*72
    __nv_bfloat16* sAl = sm + 9216;
    __nv_bfloat16* sBh = sm + 18432;
    __nv_bfloat16* sBl = sm + 27648;

    const int tid = threadIdx.x;
    const int wid = tid >> 5;
    const int lane = tid & 31;
    const int wm = wid >> 2;       // 0..1 : 64-row warp tile
    const int wn = wid & 3;        // 0..3 : 32-col warp tile
    const int n0 = blockIdx.x * 128;
    const int m0 = blockIdx.y * 128;

    float acc[4][4][4];
#pragma unroll
    for (int mt = 0; mt < 4; ++mt)
#pragma unroll
        for (int nt = 0; nt < 4; ++nt)
#pragma unroll
            for (int e = 0; e < 4; ++e) acc[mt][nt][e] = 0.f;

    // per-thread ldmatrix base addresses (lane&15 rows, lane>>4 k-halves)
    const uint32_t aBase = smem_u32(sAh) +
        (uint32_t)((wm * 64 + (lane & 15)) * ROWB + ((lane >> 4) << 4));
    const uint32_t alBase = aBase + 9216 * 2;
    const uint32_t bBase = smem_u32(sBh) +
        (uint32_t)((wn * 32 + (lane & 15)) * ROWB + ((lane >> 4) << 4));
    const uint32_t blBase = bBase + 9216 * 2;

    const int nch = K >> 6;
    for (int kc = 0; kc < nch; ++kc) {
        if (kc) __syncthreads();
        for (int idx = tid; idx < 1024; idx += 256) {  // A tiles 128x64
            const int r = idx >> 3, c = idx & 7;
            const size_t go = (size_t)(m0 + r) * K + kc * 64 + c * 8;
            const int so = r * 72 + c * 8;
            *(uint4*)(sAh + so) = *(const uint4*)(Ah + go);
            *(uint4*)(sAl + so) = *(const uint4*)(Al + go);
        }
        for (int idx = tid; idx < 1024; idx += 256) {  // B tiles 128x64
            const int r = idx >> 3, c = idx & 7;
            const size_t go = (size_t)(n0 + r) * K + kc * 64 + c * 8;
            const int so = r * 72 + c * 8;
            *(uint4*)(sBh + so) = *(const uint4*)(Bh + go);
            *(uint4*)(sBl + so) = *(const uint4*)(Bl + go);
        }
        __syncthreads();
#pragma unroll
        for (int s = 0; s < 4; ++s) {
            const uint32_t koff = (uint32_t)(s * 32);
            uint32_t bh[2][4], bl[2][4];
            ldm4(bh[0], bBase + koff);
            ldm4(bh[1], bBase + koff + 16 * ROWB);
            ldm4(bl[0], blBase + koff);
            ldm4(bl[1], blBase + koff + 16 * ROWB);
#pragma unroll
            for (int mt = 0; mt < 4; ++mt) {
                uint32_t ah[4], al[4];
                ldm4(ah, aBase + koff + (uint32_t)(mt * 16 * ROWB));
                ldm4(al, alBase + koff + (uint32_t)(mt * 16 * ROWB));
#pragma unroll
                for (int nt = 0; nt < 4; ++nt) {
                    const int np = nt >> 1, sel = nt & 1;
                    const uint32_t h0 = bh[np][sel], h1 = bh[np][sel + 2];
                    const uint32_t l0 = bl[np][sel], l1 = bl[np][sel + 2];
                    mma_bf16(acc[mt][nt], ah, h0, h1);
                    mma_bf16(acc[mt][nt], ah, l0, l1);
                    mma_bf16(acc[mt][nt], al, h0, h1);
                }
            }
        }
    }

    // epilogue (fragment layout: rows lane>>2 and +8; cols 2*(lane&3), +1)
    const int r0 = lane >> 2;
    const int c0 = (lane & 3) * 2;
#pragma unroll
    for (int mt = 0; mt < 4; ++mt) {
#pragma unroll
        for (int nt = 0; nt < 4; ++nt) {
            const int gc = n0 + wn * 32 + nt * 8 + c0;
            const float bx = bias[gc], by = bias[gc + 1];
#pragma unroll
            for (int half = 0; half < 2; ++half) {
                const int gr = m0 + wm * 64 + mt * 16 + r0 + half * 8;
                float vx = acc[mt][nt][2 * half] + bx;
                float vy = acc[mt][nt][2 * half + 1] + by;
                const size_t ro = (size_t)gr * out_ld + gc;
                if (MODE == 0) {
                    *(float2*)(outF + ro) = make_float2(vx, vy);
                } else if (MODE == 2) {
                    float2 xv = *(float2*)(resid + ro);
                    xv.x += vx; xv.y += vy;
                    *(float2*)(resid + ro) = xv;
                } else {
                    vx = fmaxf(vx, 0.f); vy = fmaxf(vy, 0.f);
                    __nv_bfloat16 h0, h1, l0, l1;
                    split_pair(vx, h0, l0); split_pair(vy, h1, l1);
                    *(uint32_t*)(outPh + ro) =
                        (uint32_t)__bfloat16_as_ushort(h0) |
                        ((uint32_t)__bfloat16_as_ushort(h1) << 16);
                    *(uint32_t*)(outPl + ro) =
                        (uint32_t)__bfloat16_as_ushort(l0) |
                        ((uint32_t)__bfloat16_as_ushort(l1) << 16);
                }
            }
        }
    }
}

__global__ void __launch_bounds__(256, 2)
k_gemm_qkv(const float* __restrict__ bias) {
    gemm_body<0>(g_h_hi, g_h_lo, g_Bqkv_h, g_Bqkv_l, bias, g_qkv,
                 nullptr, nullptr, nullptr, 256, 768);
}
__global__ void __launch_bounds__(256, 2)
k_gemm_wo(const float* __restrict__ bias, float* __restrict__ x) {
    gemm_body<2>(g_o_hi, g_o_lo, g_Bo_h, g_Bo_l, bias, nullptr,
                 nullptr, nullptr, x, 256, 256);
}
__global__ void __launch_bounds__(256, 2)
k_gemm_ffn1(const float* __restrict__ bias) {
    gemm_body<1>(g_h_hi, g_h_lo, g_B1_h, g_B1_l, bias, nullptr,
                 g_u_hi, g_u_lo, nullptr, 256, 1024);
}
__global__ void __launch_bounds__(256, 2)
k_gemm_ffn2(const float* __restrict__ bias, float* __restrict__ x) {
    gemm_body<2>(g_u_hi, g_u_lo, g_B2_h, g_B2_l, bias, nullptr,
                 nullptr, nullptr, x, 1024, 256);
}

// ---------------- LayerNorm: x -> bf16 pair ---------------------------------
__global__ void __launch_bounds__(256)
k_ln(const float* __restrict__ x, const float* __restrict__ g,
     const float* __restrict__ bta) {
    const int row = blockIdx.x * 8 + (threadIdx.x >> 5);
    const int lane = threadIdx.x & 31;
    const float* rp = x + (size_t)row * 256 + lane * 8;
    const float4 a = *(const float4*)rp;
    const float4 b4 = *(const float4*)(rp + 4);
    float vals[8] = {a.x, a.y, a.z, a.w, b4.x, b4.y, b4.z, b4.w};
    float s = 0.f, s2 = 0.f;
#pragma unroll
    for (int j = 0; j < 8; ++j) { s += vals[j]; s2 = fmaf(vals[j], vals[j], s2); }
#pragma unroll
    for (int off = 16; off; off >>= 1) {
        s += __shfl_xor_sync(0xffffffffu, s, off);
        s2 += __shfl_xor_sync(0xffffffffu, s2, off);
    }
    const float mean = s * 0.00390625f;
    const float var = s2 * 0.00390625f - mean * mean;
    const float rstd = rsqrtf(var + 1e-5f);
    uint32_t phv[4], plv[4];
#pragma unroll
    for (int j = 0; j < 4; ++j) {
        const int c0 = lane * 8 + 2 * j;
        float v0 = (vals[2 * j] - mean) * rstd * g[c0] + bta[c0];
        float v1 = (vals[2 * j + 1] - mean) * rstd * g[c0 + 1] + bta[c0 + 1];
        __nv_bfloat16 h0, h1, l0, l1;
        split_pair(v0, h0, l0); split_pair(v1, h1, l1);
        phv[j] = (uint32_t)__bfloat16_as_ushort(h0) |
                 ((uint32_t)__bfloat16_as_ushort(h1) << 16);
        plv[j] = (uint32_t)__bfloat16_as_ushort(l0) |
                 ((uint32_t)__bfloat16_as_ushort(l1) << 16);
    }
    const size_t o = (size_t)row * 256 + lane * 8;
    *(uint4*)(g_h_hi + o) = make_uint4(phv[0], phv[1], phv[2], phv[3]);
    *(uint4*)(g_h_lo + o) = make_uint4(plv[0], plv[1], plv[2], plv[3]);
}

// ---------------- Attention (fp32, banded |i-j|<=1) --------------------------
__global__ void __launch_bounds__(256, 2)
k_attn() {
    extern __shared__ float smf[];  // [32][776]
    const int b = blockIdx.x;
    const int tid = threadIdx.x;
    const int wid = tid >> 5;
    const int lane = tid & 31;
    const float* gq = g_qkv + (size_t)b * 24576;
    for (int r = wid; r < 32; r += 8)
#pragma unroll
        for (int j = 0; j < 24; ++j)
            smf[r * 776 + j * 32 + lane] = gq[r * 768 + j * 32 + lane];
    __syncthreads();

    const int h = wid;
    float kreg[32];
#pragma unroll
    for (int d = 0; d < 32; ++d)
        kreg[d] = smf[lane * 776 + 256 + h * 32 + d];
    const float SC = 0.17677669529663689f;
    for (int i = 0; i < 32; ++i) {
        const float* qrow = smf + i * 776 + h * 32;
        float s = 0.f;
#pragma unroll
        for (int d = 0; d < 32; ++d) s = fmaf(qrow[d], kreg[d], s);
        s *= SC;
        int dj = lane - i;
        if (dj < 0) dj = -dj;
        if (dj > 1) s -= 1e9f;
        float m = s;
#pragma unroll
        for (int off = 16; off; off >>= 1)
            m = fmaxf(m, __shfl_xor_sync(0xffffffffu, m, off));
        const float e = expf(s - m);
        float sum = e;
#pragma unroll
        for (int off = 16; off; off >>= 1)
            sum += __shfl_xor_sync(0xffffffffu, sum, off);
        const float w = e / sum;
        float o = 0.f;
        const int j0 = (i > 0) ? i - 1 : 0;
        const int j1 = (i < 31) ? i + 1 : 31;
        for (int j = j0; j <= j1; ++j) {
            const float wj = __shfl_sync(0xffffffffu, w, j);
            o = fmaf(wj, smf[j * 776 + 512 + h * 32 + lane], o);
        }
        const size_t ro = (size_t)(b * 32 + i) * 256 + h * 32 + lane;
        __nv_bfloat16 hh, ll;
        split_pair(o, hh, ll);
        g_o_hi[ro] = hh;
        g_o_lo[ro] = ll;
    }
}

// ---------------- Weight prep ------------------------------------------------
__global__ void k_split_qkv(const float* __restrict__ w) {
    int i = blockIdx.x * 256 + threadIdx.x;
    if (i < 768 * 256) split_pair(w[i], g_Bqkv_h[i], g_Bqkv_l[i]);
}
__global__ void k_split_wo(const float* __restrict__ w) {
    int i = blockIdx.x * 256 + threadIdx.x;
    if (i < 256 * 256) split_pair(w[i], g_Bo_h[i], g_Bo_l[i]);
}
__global__ void k_split_w1(const float* __restrict__ w) {  // W1[256,1024] -> [f][k]
    int i = blockIdx.x * 256 + threadIdx.x;
    if (i < 1024 * 256) {
        int f = i >> 8, k = i & 255;
        split_pair(w[k * 1024 + f], g_B1_h[i], g_B1_l[i]);
    }
}
__global__ void k_split_w2(const float* __restrict__ w) {  // W2[1024,256] -> [c][k]
    int i = blockIdx.x * 256 + threadIdx.x;
    if (i < 256 * 1024) {
        int c = i >> 10, k = i & 1023;
        split_pair(w[k * 256 + c], g_B2_h[i], g_B2_l[i]);
    }
}

// ---------------- Tokenizer (fp32, proven) -----------------------------------
__global__ void __launch_bounds__(256)
bt_tokenize(const float* __restrict__ obs, const float* __restrict__ embW,
            const float* __restrict__ embB, const float* __restrict__ pos,
            float* __restrict__ out) {
    __shared__ float obs_s[32 * 128];
    const int n = blockIdx.x;
    const int b0 = blockIdx.y * 32;
    const int tid = threadIdx.x;
    const float* src = obs + b0 * 128;
    for (int i = tid; i < 4096; i += 256) obs_s[i] = src[i];
    __syncthreads();
    const int e = tid;
    float acc[32];
#pragma unroll
    for (int bb = 0; bb < 32; ++bb) acc[bb] = 0.f;
    const float* wb = embW + n * 32768 + e;
    for (int d0 = 0; d0 < 128; d0 += 16) {
        float w[16];
#pragma unroll
        for (int dd = 0; dd < 16; ++dd) w[dd] = wb[(d0 + dd) * 256];
#pragma unroll
        for (int bb = 0; bb < 32; ++bb) {
            const float4* orow = (const float4*)(obs_s + bb * 128 + d0);
            float4 o0 = orow[0], o1 = orow[1], o2 = orow[2], o3 = orow[3];
            float a = acc[bb];
            a = fmaf(o0.x, w[0], a);  a = fmaf(o0.y, w[1], a);
            a = fmaf(o0.z, w[2], a);  a = fmaf(o0.w, w[3], a);
            a = fmaf(o1.x, w[4], a);  a = fmaf(o1.y, w[5], a);
            a = fmaf(o1.z, w[6], a);  a = fmaf(o1.w, w[7], a);
            a = fmaf(o2.x, w[8], a);  a = fmaf(o2.y, w[9], a);
            a = fmaf(o2.z, w[10], a); a = fmaf(o2.w, w[11], a);
            a = fmaf(o3.x, w[12], a); a = fmaf(o3.y, w[13], a);
            a = fmaf(o3.z, w[14], a); a = fmaf(o3.w, w[15], a);
            acc[bb] = a;
        }
    }
    const float add = embB[n * 256 + e] + pos[n * 256 + e];
#pragma unroll
    for (int bb = 0; bb < 32; ++bb)
        out[(b0 + bb) * 8192 + n * 256 + e] = acc[bb] + add;
}

extern "C" void kernel_launch(void* const* d_in, const int* in_sizes, int n_in,
                              void* d_out, int out_size) {
    (void)in_sizes; (void)n_in; (void)out_size;
    const float* obs  = (const float*)d_in[0];
    const float* embW = (const float*)d_in[1];
    const float* embB = (const float*)d_in[2];
    const float* pos  = (const float*)d_in[3];
    const float* Wqkv = (const float*)d_in[4];
    const float* bqkv = (const float*)d_in[5];
    const float* Wo   = (const float*)d_in[6];
    const float* bo   = (const float*)d_in[7];
    const float* ln1g = (const float*)d_in[8];
    const float* ln1b = (const float*)d_in[9];
    const float* ln2g = (const float*)d_in[10];
    const float* ln2b = (const float*)d_in[11];
    const float* W1   = (const float*)d_in[12];
    const float* b1   = (const float*)d_in[13];
    const float* W2   = (const float*)d_in[14];
    const float* b2   = (const float*)d_in[15];
    float* x = (float*)d_out;

    const int GSMEM = 4 * 9216 * 2;   // 73728 B
    const int ASMEM = 32 * 776 * 4;   // 99328 B
    cudaFuncSetAttribute(k_gemm_qkv,  cudaFuncAttributeMaxDynamicSharedMemorySize, GSMEM);
    cudaFuncSetAttribute(k_gemm_wo,   cudaFuncAttributeMaxDynamicSharedMemorySize, GSMEM);
    cudaFuncSetAttribute(k_gemm_ffn1, cudaFuncAttributeMaxDynamicSharedMemorySize, GSMEM);
    cudaFuncSetAttribute(k_gemm_ffn2, cudaFuncAttributeMaxDynamicSharedMemorySize, GSMEM);
    cudaFuncSetAttribute(k_attn,      cudaFuncAttributeMaxDynamicSharedMemorySize, ASMEM);

    k_split_qkv<<<768, 256>>>(Wqkv);
    k_split_wo<<<256, 256>>>(Wo);
    k_split_w1<<<1024, 256>>>(W1);
    k_split_w2<<<1024, 256>>>(W2);
    bt_tokenize<<<dim3(32, 128), 256>>>(obs, embW, embB, pos, x);

    for (int l = 0; l < 6; ++l) {
        k_ln<<<16384, 256>>>(x, ln1g, ln1b);
        k_gemm_qkv<<<dim3(6, 1024), 256, GSMEM>>>(bqkv);
        k_attn<<<4096, 256, ASMEM>>>();
        k_gemm_wo<<<dim3(2, 1024), 256, GSMEM>>>(bo, x);
        k_ln<<<16384, 256>>>(x, ln2g, ln2b);
        k_gemm_ffn1<<<dim3(8, 1024), 256, GSMEM>>>(b1);
        k_gemm_ffn2<<<dim3(2, 1024), 256, GSMEM>>>(b2, x);
    }
}

// round 9
// speedup vs baseline: 2.4079x; 1.1006x over previous
#include <cuda_runtime.h>
#include <cuda_bf16.h>
#include <cstdint>

// ---------------------------------------------------------------------------
// BodyTransformer via mma.sync bf16-pair GEMMs + cp.async pipeline (sm_103)
// M=131072 rows, E=256, H=8, DH=32, F=1024, L=6 (shared weights)
// D = Ah*Bh + Ah*Bl + Al*Bh, fp32 register accumulation.
// ---------------------------------------------------------------------------

#define MM 131072

__device__ __align__(16) __nv_bfloat16 g_h_hi[(size_t)MM * 256];
__device__ __align__(16) __nv_bfloat16 g_h_lo[(size_t)MM * 256];
__device__ __align__(16) float         g_qkv[(size_t)MM * 768];
__device__ __align__(16) __nv_bfloat16 g_o_hi[(size_t)MM * 256];
__device__ __align__(16) __nv_bfloat16 g_o_lo[(size_t)MM * 256];
__device__ __align__(16) __nv_bfloat16 g_u_hi[(size_t)MM * 1024];
__device__ __align__(16) __nv_bfloat16 g_u_lo[(size_t)MM * 1024];
__device__ __align__(16) __nv_bfloat16 g_Bqkv_h[768 * 256], g_Bqkv_l[768 * 256];
__device__ __align__(16) __nv_bfloat16 g_Bo_h[256 * 256],   g_Bo_l[256 * 256];
__device__ __align__(16) __nv_bfloat16 g_B1_h[1024 * 256],  g_B1_l[1024 * 256];
__device__ __align__(16) __nv_bfloat16 g_B2_h[256 * 1024],  g_B2_l[256 * 1024];

static __device__ __forceinline__ uint32_t smem_u32(const void* p) {
    uint32_t a;
    asm("{ .reg .u64 t; cvta.to.shared.u64 t, %1; cvt.u32.u64 %0, t; }"
        : "=r"(a) : "l"(p));
    return a;
}
static __device__ __forceinline__ void ldm4(uint32_t* r, uint32_t addr) {
    asm volatile("ldmatrix.sync.aligned.m8n8.x4.shared.b16 {%0,%1,%2,%3}, [%4];"
                 : "=r"(r[0]), "=r"(r[1]), "=r"(r[2]), "=r"(r[3]) : "r"(addr));
}
static __device__ __forceinline__ void mma_bf16(float* d, const uint32_t* a,
                                                uint32_t b0, uint32_t b1) {
    asm volatile(
        "mma.sync.aligned.m16n8k16.row.col.f32.bf16.bf16.f32 "
        "{%0,%1,%2,%3}, {%4,%5,%6,%7}, {%8,%9}, {%0,%1,%2,%3};"
        : "+f"(d[0]), "+f"(d[1]), "+f"(d[2]), "+f"(d[3])
        : "r"(a[0]), "r"(a[1]), "r"(a[2]), "r"(a[3]), "r"(b0), "r"(b1));
}
static __device__ __forceinline__ void cpasync16(uint32_t sa, const void* g) {
    asm volatile("cp.async.cg.shared.global [%0], [%1], 16;"
                 :: "r"(sa), "l"(g) : "memory");
}
static __device__ __forceinline__ void cp_commit() {
    asm volatile("cp.async.commit_group;" ::: "memory");
}
static __device__ __forceinline__ void cp_wait1() {
    asm volatile("cp.async.wait_group 1;" ::: "memory");
}
static __device__ __forceinline__ void split_pair(float v, __nv_bfloat16& h,
                                                  __nv_bfloat16& l) {
    h = __float2bfloat16(v);
    l = __float2bfloat16(v - __bfloat162float(h));
}

// ---------------------------------------------------------------------------
// Pipelined GEMM: D[128x128] = A_pair[m0..,K] * B_pair[n0..,K]^T (+ epilogue)
// 2-stage cp.async double buffer, K-chunk 32. Row stride 40 bf16 (80 B) —
// conflict-free ldmatrix. blockIdx.x=N tile, .y=M tile (A reuse in L2).
// MODE 0: fp32 +bias; 1: relu+bias -> bf16 pair; 2: resid += (+bias)
// smem: 2 stages x 4 arrays x 128x40 bf16 = 81920 B
// ---------------------------------------------------------------------------
#define RW 40            // bf16 per row
#define ARR 5120         // elems per array (128*40)
#define STAGE (4 * ARR)  // elems per stage

template <int MODE>
static __device__ __forceinline__ void gemm_body(
    const __nv_bfloat16* __restrict__ Ah, const __nv_bfloat16* __restrict__ Al,
    const __nv_bfloat16* __restrict__ Bh, const __nv_bfloat16* __restrict__ Bl,
    const float* __restrict__ bias, float* __restrict__ outF,
    __nv_bfloat16* __restrict__ outPh, __nv_bfloat16* __restrict__ outPl,
    float* __restrict__ resid, int K, int out_ld) {
    extern __shared__ __nv_bfloat16 sm[];

    const int tid = threadIdx.x;
    const int wid = tid >> 5;
    const int lane = tid & 31;
    const int wm = wid >> 2;       // 0..1
    const int wn = wid & 3;        // 0..3
    const int n0 = blockIdx.x * 128;
    const int m0 = blockIdx.y * 128;

    const __nv_bfloat16* gbase[4] = {Ah + (size_t)m0 * K, Al + (size_t)m0 * K,
                                     Bh + (size_t)n0 * K, Bl + (size_t)n0 * K};
    const uint32_t smBase = smem_u32(sm);

    // copy indices for this thread (8 x 16B per stage)
    const int arr = tid >> 6;          // 0..3 : thread block owns one array
    const int r8 = (tid & 63) << 1;    // rows r8, r8+1 ; 4x16B per row? no:
    // 2048 16B-copies per stage, 256 threads -> 8 each: arr=idx>>9, r=(idx>>2)&127, c=idx&3
    float acc[4][4][4];
#pragma unroll
    for (int mt = 0; mt < 4; ++mt)
#pragma unroll
        for (int nt = 0; nt < 4; ++nt)
#pragma unroll
            for (int e = 0; e < 4; ++e) acc[mt][nt][e] = 0.f;

    const int nst = K >> 5;

    // issue one full stage of cp.async
    auto load_stage = [&](int s, int kc) {
        const uint32_t sb = smBase + (uint32_t)((s & 1) * STAGE * 2);
#pragma unroll
        for (int i = 0; i < 8; ++i) {
            const int idx = tid + i * 256;
            const int a2 = idx >> 9;
            const int r = (idx >> 2) & 127;
            const int c = idx & 3;
            const uint32_t sa = sb + (uint32_t)(a2 * ARR * 2 + r * RW * 2 + c * 16);
            cpasync16(sa, gbase[a2] + (size_t)r * K + kc * 32 + c * 8);
        }
        cp_commit();
    };

    load_stage(0, 0);
    if (nst > 1) load_stage(1, 1); else cp_commit();

    // per-warp ldmatrix bases (within a stage)
    const uint32_t aOff  = (uint32_t)((wm * 64 + (lane & 15)) * RW * 2 + ((lane >> 4) << 4));
    const uint32_t bOff  = (uint32_t)((wn * 32 + (lane & 15)) * RW * 2 + ((lane >> 4) << 4));

    for (int s = 0; s < nst; ++s) {
        cp_wait1();
        __syncthreads();
        const uint32_t sb = smBase + (uint32_t)((s & 1) * STAGE * 2);
        const uint32_t aB = sb + aOff;
        const uint32_t alB = aB + ARR * 2;
        const uint32_t bB = sb + 2u * ARR * 2 + bOff;
        const uint32_t blB = bB + ARR * 2;
#pragma unroll
        for (int st = 0; st < 2; ++st) {
            const uint32_t koff = (uint32_t)(st * 32);
            uint32_t bh[2][4], bl[2][4];
            ldm4(bh[0], bB + koff);
            ldm4(bh[1], bB + koff + 16 * RW * 2);
            ldm4(bl[0], blB + koff);
            ldm4(bl[1], blB + koff + 16 * RW * 2);
#pragma unroll
            for (int mt = 0; mt < 4; ++mt) {
                uint32_t ah[4], al[4];
                ldm4(ah, aB + koff + (uint32_t)(mt * 16 * RW * 2));
                ldm4(al, alB + koff + (uint32_t)(mt * 16 * RW * 2));
#pragma unroll
                for (int nt = 0; nt < 4; ++nt) {
                    const int np = nt >> 1, sel = nt & 1;
                    const uint32_t h0 = bh[np][sel], h1 = bh[np][sel + 2];
                    const uint32_t l0 = bl[np][sel], l1 = bl[np][sel + 2];
                    mma_bf16(acc[mt][nt], ah, h0, h1);
                    mma_bf16(acc[mt][nt], ah, l0, l1);
                    mma_bf16(acc[mt][nt], al, h0, h1);
                }
            }
        }
        __syncthreads();
        if (s + 2 < nst) load_stage(s + 2, s + 2);
        else cp_commit();  // keep group count consistent for wait_group 1
    }

    // epilogue (fragment: rows lane>>2, +8; cols 2*(lane&3), +1)
    const int r0 = lane >> 2;
    const int c0 = (lane & 3) * 2;
#pragma unroll
    for (int mt = 0; mt < 4; ++mt) {
#pragma unroll
        for (int nt = 0; nt < 4; ++nt) {
            const int gc = n0 + wn * 32 + nt * 8 + c0;
            const float bx = bias[gc], by = bias[gc + 1];
#pragma unroll
            for (int half = 0; half < 2; ++half) {
                const int gr = m0 + wm * 64 + mt * 16 + r0 + half * 8;
                float vx = acc[mt][nt][2 * half] + bx;
                float vy = acc[mt][nt][2 * half + 1] + by;
                const size_t ro = (size_t)gr * out_ld + gc;
                if (MODE == 0) {
                    *(float2*)(outF + ro) = make_float2(vx, vy);
                } else if (MODE == 2) {
                    float2 xv = *(float2*)(resid + ro);
                    xv.x += vx; xv.y += vy;
                    *(float2*)(resid + ro) = xv;
                } else {
                    vx = fmaxf(vx, 0.f); vy = fmaxf(vy, 0.f);
                    __nv_bfloat16 h0, h1, l0, l1;
                    split_pair(vx, h0, l0); split_pair(vy, h1, l1);
                    *(uint32_t*)(outPh + ro) =
                        (uint32_t)__bfloat16_as_ushort(h0) |
                        ((uint32_t)__bfloat16_as_ushort(h1) << 16);
                    *(uint32_t*)(outPl + ro) =
                        (uint32_t)__bfloat16_as_ushort(l0) |
                        ((uint32_t)__bfloat16_as_ushort(l1) << 16);
                }
            }
        }
    }
}

__global__ void __launch_bounds__(256, 2)
k_gemm_qkv(const float* __restrict__ bias) {
    gemm_body<0>(g_h_hi, g_h_lo, g_Bqkv_h, g_Bqkv_l, bias, g_qkv,
                 nullptr, nullptr, nullptr, 256, 768);
}
__global__ void __launch_bounds__(256, 2)
k_gemm_wo(const float* __restrict__ bias, float* __restrict__ x) {
    gemm_body<2>(g_o_hi, g_o_lo, g_Bo_h, g_Bo_l, bias, nullptr,
                 nullptr, nullptr, x, 256, 256);
}
__global__ void __launch_bounds__(256, 2)
k_gemm_ffn1(const float* __restrict__ bias) {
    gemm_body<1>(g_h_hi, g_h_lo, g_B1_h, g_B1_l, bias, nullptr,
                 g_u_hi, g_u_lo, nullptr, 256, 1024);
}
__global__ void __launch_bounds__(256, 2)
k_gemm_ffn2(const float* __restrict__ bias, float* __restrict__ x) {
    gemm_body<2>(g_u_hi, g_u_lo, g_B2_h, g_B2_l, bias, nullptr,
                 nullptr, nullptr, x, 1024, 256);
}

// ---------------- LayerNorm: x -> bf16 pair ---------------------------------
__global__ void __launch_bounds__(256)
k_ln(const float* __restrict__ x, const float* __restrict__ g,
     const float* __restrict__ bta) {
    const int row = blockIdx.x * 8 + (threadIdx.x >> 5);
    const int lane = threadIdx.x & 31;
    const float* rp = x + (size_t)row * 256 + lane * 8;
    const float4 a = *(const float4*)rp;
    const float4 b4 = *(const float4*)(rp + 4);
    float vals[8] = {a.x, a.y, a.z, a.w, b4.x, b4.y, b4.z, b4.w};
    float s = 0.f, s2 = 0.f;
#pragma unroll
    for (int j = 0; j < 8; ++j) { s += vals[j]; s2 = fmaf(vals[j], vals[j], s2); }
#pragma unroll
    for (int off = 16; off; off >>= 1) {
        s += __shfl_xor_sync(0xffffffffu, s, off);
        s2 += __shfl_xor_sync(0xffffffffu, s2, off);
    }
    const float mean = s * 0.00390625f;
    const float var = s2 * 0.00390625f - mean * mean;
    const float rstd = rsqrtf(var + 1e-5f);
    uint32_t phv[4], plv[4];
#pragma unroll
    for (int j = 0; j < 4; ++j) {
        const int c0 = lane * 8 + 2 * j;
        float v0 = (vals[2 * j] - mean) * rstd * g[c0] + bta[c0];
        float v1 = (vals[2 * j + 1] - mean) * rstd * g[c0 + 1] + bta[c0 + 1];
        __nv_bfloat16 h0, h1, l0, l1;
        split_pair(v0, h0, l0); split_pair(v1, h1, l1);
        phv[j] = (uint32_t)__bfloat16_as_ushort(h0) |
                 ((uint32_t)__bfloat16_as_ushort(h1) << 16);
        plv[j] = (uint32_t)__bfloat16_as_ushort(l0) |
                 ((uint32_t)__bfloat16_as_ushort(l1) << 16);
    }
    const size_t o = (size_t)row * 256 + lane * 8;
    *(uint4*)(g_h_hi + o) = make_uint4(phv[0], phv[1], phv[2], phv[3]);
    *(uint4*)(g_h_lo + o) = make_uint4(plv[0], plv[1], plv[2], plv[3]);
}

// ---------------- Attention (fp32, banded |i-j|<=1) --------------------------
__global__ void __launch_bounds__(256, 2)
k_attn() {
    extern __shared__ float smf[];  // [32][776]
    const int b = blockIdx.x;
    const int tid = threadIdx.x;
    const int wid = tid >> 5;
    const int lane = tid & 31;
    const float* gq = g_qkv + (size_t)b * 24576;
    for (int r = wid; r < 32; r += 8)
#pragma unroll
        for (int j = 0; j < 24; ++j)
            smf[r * 776 + j * 32 + lane] = gq[r * 768 + j * 32 + lane];
    __syncthreads();

    const int h = wid;
    float kreg[32];
#pragma unroll
    for (int d = 0; d < 32; ++d)
        kreg[d] = smf[lane * 776 + 256 + h * 32 + d];
    const float SC = 0.17677669529663689f;
    for (int i = 0; i < 32; ++i) {
        const float* qrow = smf + i * 776 + h * 32;
        float s = 0.f;
#pragma unroll
        for (int d = 0; d < 32; ++d) s = fmaf(qrow[d], kreg[d], s);
        s *= SC;
        int dj = lane - i;
        if (dj < 0) dj = -dj;
        if (dj > 1) s -= 1e9f;
        float m = s;
#pragma unroll
        for (int off = 16; off; off >>= 1)
            m = fmaxf(m, __shfl_xor_sync(0xffffffffu, m, off));
        const float e = expf(s - m);
        float sum = e;
#pragma unroll
        for (int off = 16; off; off >>= 1)
            sum += __shfl_xor_sync(0xffffffffu, sum, off);
        const float w = e / sum;
        float o = 0.f;
        const int j0 = (i > 0) ? i - 1 : 0;
        const int j1 = (i < 31) ? i + 1 : 31;
        for (int j = j0; j <= j1; ++j) {
            const float wj = __shfl_sync(0xffffffffu, w, j);
            o = fmaf(wj, smf[j * 776 + 512 + h * 32 + lane], o);
        }
        const size_t ro = (size_t)(b * 32 + i) * 256 + h * 32 + lane;
        __nv_bfloat16 hh, ll;
        split_pair(o, hh, ll);
        g_o_hi[ro] = hh;
        g_o_lo[ro] = ll;
    }
}

// ---------------- Weight prep ------------------------------------------------
__global__ void k_split_qkv(const float* __restrict__ w) {
    int i = blockIdx.x * 256 + threadIdx.x;
    if (i < 768 * 256) split_pair(w[i], g_Bqkv_h[i], g_Bqkv_l[i]);
}
__global__ void k_split_wo(const float* __restrict__ w) {
    int i = blockIdx.x * 256 + threadIdx.x;
    if (i < 256 * 256) split_pair(w[i], g_Bo_h[i], g_Bo_l[i]);
}
__global__ void k_split_w1(const float* __restrict__ w) {  // W1[256,1024] -> [f][k]
    int i = blockIdx.x * 256 + threadIdx.x;
    if (i < 1024 * 256) {
        int f = i >> 8, k = i & 255;
        split_pair(w[k * 1024 + f], g_B1_h[i], g_B1_l[i]);
    }
}
__global__ void k_split_w2(const float* __restrict__ w) {  // W2[1024,256] -> [c][k]
    int i = blockIdx.x * 256 + threadIdx.x;
    if (i < 256 * 1024) {
        int c = i >> 10, k = i & 1023;
        split_pair(w[k * 256 + c], g_B2_h[i], g_B2_l[i]);
    }
}

// ---------------- Tokenizer (fp32, proven) -----------------------------------
__global__ void __launch_bounds__(256)
bt_tokenize(const float* __restrict__ obs, const float* __restrict__ embW,
            const float* __restrict__ embB, const float* __restrict__ pos,
            float* __restrict__ out) {
    __shared__ float obs_s[32 * 128];
    const int n = blockIdx.x;
    const int b0 = blockIdx.y * 32;
    const int tid = threadIdx.x;
    const float* src = obs + b0 * 128;
    for (int i = tid; i < 4096; i += 256) obs_s[i] = src[i];
    __syncthreads();
    const int e = tid;
    float acc[32];
#pragma unroll
    for (int bb = 0; bb < 32; ++bb) acc[bb] = 0.f;
    const float* wb = embW + n * 32768 + e;
    for (int d0 = 0; d0 < 128; d0 += 16) {
        float w[16];
#pragma unroll
        for (int dd = 0; dd < 16; ++dd) w[dd] = wb[(d0 + dd) * 256];
#pragma unroll
        for (int bb = 0; bb < 32; ++bb) {
            const float4* orow = (const float4*)(obs_s + bb * 128 + d0);
            float4 o0 = orow[0], o1 = orow[1], o2 = orow[2], o3 = orow[3];
            float a = acc[bb];
            a = fmaf(o0.x, w[0], a);  a = fmaf(o0.y, w[1], a);
            a = fmaf(o0.z, w[2], a);  a = fmaf(o0.w, w[3], a);
            a = fmaf(o1.x, w[4], a);  a = fmaf(o1.y, w[5], a);
            a = fmaf(o1.z, w[6], a);  a = fmaf(o1.w, w[7], a);
            a = fmaf(o2.x, w[8], a);  a = fmaf(o2.y, w[9], a);
            a = fmaf(o2.z, w[10], a); a = fmaf(o2.w, w[11], a);
            a = fmaf(o3.x, w[12], a); a = fmaf(o3.y, w[13], a);
            a = fmaf(o3.z, w[14], a); a = fmaf(o3.w, w[15], a);
            acc[bb] = a;
        }
    }
    const float add = embB[n * 256 + e] + pos[n * 256 + e];
#pragma unroll
    for (int bb = 0; bb < 32; ++bb)
        out[(b0 + bb) * 8192 + n * 256 + e] = acc[bb] + add;
}

extern "C" void kernel_launch(void* const* d_in, const int* in_sizes, int n_in,
                              void* d_out, int out_size) {
    (void)in_sizes; (void)n_in; (void)out_size;
    const float* obs  = (const float*)d_in[0];
    const float* embW = (const float*)d_in[1];
    const float* embB = (const float*)d_in[2];
    const float* pos  = (const float*)d_in[3];
    const float* Wqkv = (const float*)d_in[4];
    const float* bqkv = (const float*)d_in[5];
    const float* Wo   = (const float*)d_in[6];
    const float* bo   = (const float*)d_in[7];
    const float* ln1g = (const float*)d_in[8];
    const float* ln1b = (const float*)d_in[9];
    const float* ln2g = (const float*)d_in[10];
    const float* ln2b = (const float*)d_in[11];
    const float* W1   = (const float*)d_in[12];
    const float* b1   = (const float*)d_in[13];
    const float* W2   = (const float*)d_in[14];
    const float* b2   = (const float*)d_in[15];
    float* x = (float*)d_out;

    const int GSMEM = 2 * STAGE * 2;  // 81920 B
    const int ASMEM = 32 * 776 * 4;   // 99328 B
    cudaFuncSetAttribute(k_gemm_qkv,  cudaFuncAttributeMaxDynamicSharedMemorySize, GSMEM);
    cudaFuncSetAttribute(k_gemm_wo,   cudaFuncAttributeMaxDynamicSharedMemorySize, GSMEM);
    cudaFuncSetAttribute(k_gemm_ffn1, cudaFuncAttributeMaxDynamicSharedMemorySize, GSMEM);
    cudaFuncSetAttribute(k_gemm_ffn2, cudaFuncAttributeMaxDynamicSharedMemorySize, GSMEM);
    cudaFuncSetAttribute(k_attn,      cudaFuncAttributeMaxDynamicSharedMemorySize, ASMEM);

    k_split_qkv<<<768, 256>>>(Wqkv);
    k_split_wo<<<256, 256>>>(Wo);
    k_split_w1<<<1024, 256>>>(W1);
    k_split_w2<<<1024, 256>>>(W2);
    bt_tokenize<<<dim3(32, 128), 256>>>(obs, embW, embB, pos, x);

    for (int l = 0; l < 6; ++l) {
        k_ln<<<16384, 256>>>(x, ln1g, ln1b);
        k_gemm_qkv<<<dim3(6, 1024), 256, GSMEM>>>(bqkv);
        k_attn<<<4096, 256, ASMEM>>>();
        k_gemm_wo<<<dim3(2, 1024), 256, GSMEM>>>(bo, x);
        k_ln<<<16384, 256>>>(x, ln2g, ln2b);
        k_gemm_ffn1<<<dim3(8, 1024), 256, GSMEM>>>(b1);
        k_gemm_ffn2<<<dim3(2, 1024), 256, GSMEM>>>(b2, x);
    }
}